// round 1
// baseline (speedup 1.0000x reference)
#include <cuda_runtime.h>
#include <math.h>

// ---------------- problem constants ----------------
// x: (2, 32, 32, 32, 192); window 4x4x4 (N=64), shift 2, heads=6, hd=32
// tokens = 2*32^3 = 65536; windows B_ = 1024 (512/batch)
#define NTOK 65536
#define CDIM 192

// ---------------- scratch (device globals; no allocation in kernel_launch) ----
__device__ float g_xw  [(size_t)NTOK * 192];   // LN1 + shift + window-partitioned
__device__ float g_qkv [(size_t)NTOK * 576];   // qkv projection
__device__ float g_attn[(size_t)NTOK * 192];   // attention output (window layout)
__device__ float g_xo  [(size_t)NTOK * 192];   // x + attn-proj (token layout)
__device__ float g_xn2 [(size_t)NTOK * 192];   // LN2(xo)
__device__ float g_h1  [(size_t)NTOK * 768];   // MLP hidden

// ---------------- LayerNorm (+ optional shift/window permutation) -------------
// One warp per token; 192 channels = 6 per lane.
// PERM=true: output row t is window-layout (b_,n); source voxel is the rolled
// position: src = roll(-2) of the window grid position.
template <bool PERM>
__global__ __launch_bounds__(256)
void ln_kernel(const float* __restrict__ x, const float* __restrict__ g,
               const float* __restrict__ b, float* __restrict__ out)
{
    const int t = blockIdx.x * 8 + (threadIdx.x >> 5);
    const int lane = threadIdx.x & 31;

    size_t src;
    if (PERM) {
        const int b_ = t >> 6, n = t & 63;
        const int bb = b_ >> 9, widx = b_ & 511;
        const int hs = ((widx >> 6) << 2) + (n >> 4);
        const int ws = (((widx >> 3) & 7) << 2) + ((n >> 2) & 3);
        const int ds = ((widx & 7) << 2) + (n & 3);
        src = ((((size_t)bb * 32 + ((hs + 2) & 31)) * 32 + ((ws + 2) & 31)) * 32
               + ((ds + 2) & 31));
    } else {
        src = (size_t)t;
    }

    const float* xp = x + src * CDIM;
    float v[6];
    float s = 0.f;
#pragma unroll
    for (int r = 0; r < 6; ++r) { v[r] = xp[lane + 32 * r]; s += v[r]; }
#pragma unroll
    for (int o = 16; o > 0; o >>= 1) s += __shfl_xor_sync(0xffffffffu, s, o);
    const float mean = s * (1.f / 192.f);

    float vv = 0.f;
#pragma unroll
    for (int r = 0; r < 6; ++r) { const float d = v[r] - mean; vv += d * d; }
#pragma unroll
    for (int o = 16; o > 0; o >>= 1) vv += __shfl_xor_sync(0xffffffffu, vv, o);
    const float rstd = rsqrtf(vv * (1.f / 192.f) + 1e-5f);

    float* op = out + (size_t)t * CDIM;
#pragma unroll
    for (int r = 0; r < 6; ++r) {
        const int c = lane + 32 * r;
        op[c] = (v[r] - mean) * rstd * g[c] + b[c];
    }
}

// ---------------- generic SGEMM with templated epilogue -----------------------
// C[M,N] = A[M,K] @ B[K,N] + bias ; BM=128, BN=64, BK=16, 256 threads, 8x4/thr.
// EPI: 0 = bias only; 1 = bias + exact GELU; 2 = bias + window-reverse scatter
//      + residual (resid = original x, C = g_xo, N must be 192);
//      3 = bias + residual add (resid = g_xo), direct rows.
template <int EPI>
__global__ __launch_bounds__(256)
void gemm_kernel(const float* __restrict__ A, const float* __restrict__ B,
                 const float* __restrict__ bias, float* __restrict__ C,
                 int M, int N, int K, const float* __restrict__ resid)
{
    __shared__ float As[16][132];   // k-major: As[k][m]
    __shared__ float Bs[16][68];    // Bs[k][n]

    const int tid = threadIdx.x;
    const int m0 = blockIdx.y << 7;
    const int n0 = blockIdx.x << 6;
    const int ty = tid >> 4;          // 0..15 -> rows ty*8..ty*8+7
    const int tx = tid & 15;          // 0..15 -> cols tx*4..tx*4+3
    const int arow = tid >> 2;        // 0..63
    const int ak4  = (tid & 3) << 2;  // 0,4,8,12
    const int brow = tid >> 4;        // 0..15
    const int bcol = (tid & 15) << 2; // 0..60

    float acc[8][4];
#pragma unroll
    for (int i = 0; i < 8; ++i)
#pragma unroll
        for (int j = 0; j < 4; ++j) acc[i][j] = 0.f;

    const float* Aptr0 = A + (size_t)(m0 + arow) * K + ak4;
    const float* Aptr1 = A + (size_t)(m0 + arow + 64) * K + ak4;
    const float* Bptr  = B + (size_t)brow * N + n0 + bcol;

    for (int kt = 0; kt < K; kt += 16) {
        const float4 a0 = *(const float4*)(Aptr0 + kt);
        const float4 a1 = *(const float4*)(Aptr1 + kt);
        const float4 bv = *(const float4*)(Bptr + (size_t)kt * N);
        __syncthreads();
        As[ak4 + 0][arow] = a0.x; As[ak4 + 1][arow] = a0.y;
        As[ak4 + 2][arow] = a0.z; As[ak4 + 3][arow] = a0.w;
        As[ak4 + 0][arow + 64] = a1.x; As[ak4 + 1][arow + 64] = a1.y;
        As[ak4 + 2][arow + 64] = a1.z; As[ak4 + 3][arow + 64] = a1.w;
        *(float4*)&Bs[brow][bcol] = bv;
        __syncthreads();
#pragma unroll
        for (int kk = 0; kk < 16; ++kk) {
            const float4 x0 = *(const float4*)&As[kk][ty * 8];
            const float4 x1 = *(const float4*)&As[kk][ty * 8 + 4];
            const float4 y  = *(const float4*)&Bs[kk][tx * 4];
            const float av[8] = {x0.x, x0.y, x0.z, x0.w, x1.x, x1.y, x1.z, x1.w};
            const float bw[4] = {y.x, y.y, y.z, y.w};
#pragma unroll
            for (int i = 0; i < 8; ++i)
#pragma unroll
                for (int j = 0; j < 4; ++j)
                    acc[i][j] = fmaf(av[i], bw[j], acc[i][j]);
        }
    }

    float bs[4];
#pragma unroll
    for (int j = 0; j < 4; ++j) bs[j] = bias[n0 + tx * 4 + j];

#pragma unroll
    for (int i = 0; i < 8; ++i) {
        const int m = m0 + ty * 8 + i;
        float4 r;
        r.x = acc[i][0] + bs[0];
        r.y = acc[i][1] + bs[1];
        r.z = acc[i][2] + bs[2];
        r.w = acc[i][3] + bs[3];
        if (EPI == 1) {
            const float k = 0.70710678118654752f;
            r.x = 0.5f * r.x * (1.f + erff(r.x * k));
            r.y = 0.5f * r.y * (1.f + erff(r.y * k));
            r.z = 0.5f * r.z * (1.f + erff(r.z * k));
            r.w = 0.5f * r.w * (1.f + erff(r.w * k));
        }
        if (EPI == 0 || EPI == 1) {
            *(float4*)(C + (size_t)m * N + n0 + tx * 4) = r;
        } else if (EPI == 3) {
            const float4 rv = *(const float4*)(resid + (size_t)m * N + n0 + tx * 4);
            r.x += rv.x; r.y += rv.y; r.z += rv.z; r.w += rv.w;
            *(float4*)(C + (size_t)m * N + n0 + tx * 4) = r;
        } else { // EPI == 2: window reverse + roll(+2) + residual
            const int b_ = m >> 6, n = m & 63;
            const int bb = b_ >> 9, widx = b_ & 511;
            const int hs = ((widx >> 6) << 2) + (n >> 4);
            const int ws = (((widx >> 3) & 7) << 2) + ((n >> 2) & 3);
            const int ds = ((widx & 7) << 2) + (n & 3);
            const size_t td = ((((size_t)bb * 32 + ((hs + 2) & 31)) * 32
                               + ((ws + 2) & 31)) * 32 + ((ds + 2) & 31));
            const float4 rv = *(const float4*)(resid + td * 192 + n0 + tx * 4);
            r.x += rv.x; r.y += rv.y; r.z += rv.z; r.w += rv.w;
            *(float4*)(C + td * 192 + n0 + tx * 4) = r;
        }
    }
}

// ---------------- windowed attention ------------------------------------------
// One CTA (256 threads) per window; loops over 6 heads.
__global__ __launch_bounds__(256)
void attn_kernel(const float* __restrict__ qkv, const float* __restrict__ bt,
                 float* __restrict__ out)
{
    __shared__ float qs[64 * 33];
    __shared__ float ks[64 * 33];
    __shared__ float vs[64 * 32];
    __shared__ float ss[64 * 65];
    __shared__ int   grp[64];

    const int tid = threadIdx.x;
    const int wid = blockIdx.x;
    const int widx = wid & 511;
    const int wh = widx >> 6, ww = (widx >> 3) & 7, wd = widx & 7;

    if (tid < 64) {
        const int i = tid >> 4, j = (tid >> 2) & 3, k2 = tid & 3;
        const int rh = (wh < 7) ? 0 : ((i < 2) ? 1 : 2);
        const int rw = (ww < 7) ? 0 : ((j < 2) ? 1 : 2);
        const int rd = (wd < 7) ? 0 : ((k2 < 2) ? 1 : 2);
        grp[tid] = rh * 9 + rw * 3 + rd;
    }

    const int nld = tid >> 2;
    const int d0  = (tid & 3) * 8;
    const int ti = tid >> 4, tx = tid & 15;
    const int sr = tid >> 2, sg = tid & 3;
    const size_t qrow = ((size_t)wid * 64 + nld) * 576 + d0;
    const float scl = 0.17677669529663687f; // 1/sqrt(32)

    for (int h = 0; h < 6; ++h) {
        const float* qp = qkv + qrow + h * 32;
        const float4 q0 = *(const float4*)(qp);
        const float4 q1 = *(const float4*)(qp + 4);
        const float4 k0 = *(const float4*)(qp + 192);
        const float4 k1 = *(const float4*)(qp + 196);
        const float4 v0 = *(const float4*)(qp + 384);
        const float4 v1 = *(const float4*)(qp + 388);
        float* qd = &qs[nld * 33 + d0];
        qd[0] = q0.x * scl; qd[1] = q0.y * scl; qd[2] = q0.z * scl; qd[3] = q0.w * scl;
        qd[4] = q1.x * scl; qd[5] = q1.y * scl; qd[6] = q1.z * scl; qd[7] = q1.w * scl;
        float* kd = &ks[nld * 33 + d0];
        kd[0] = k0.x; kd[1] = k0.y; kd[2] = k0.z; kd[3] = k0.w;
        kd[4] = k1.x; kd[5] = k1.y; kd[6] = k1.z; kd[7] = k1.w;
        *(float4*)&vs[nld * 32 + d0]     = v0;
        *(float4*)&vs[nld * 32 + d0 + 4] = v1;
        __syncthreads();

        // scores: 4x4 register tile per thread over [64,64]
        float acc[4][4];
#pragma unroll
        for (int r = 0; r < 4; ++r)
#pragma unroll
            for (int c = 0; c < 4; ++c) acc[r][c] = 0.f;
#pragma unroll 8
        for (int d = 0; d < 32; ++d) {
            float aq[4], bk[4];
#pragma unroll
            for (int r = 0; r < 4; ++r) aq[r] = qs[(ti * 4 + r) * 33 + d];
#pragma unroll
            for (int c = 0; c < 4; ++c) bk[c] = ks[(tx * 4 + c) * 33 + d];
#pragma unroll
            for (int r = 0; r < 4; ++r)
#pragma unroll
                for (int c = 0; c < 4; ++c)
                    acc[r][c] = fmaf(aq[r], bk[c], acc[r][c]);
        }
#pragma unroll
        for (int r = 0; r < 4; ++r)
#pragma unroll
            for (int c = 0; c < 4; ++c) {
                const int i = ti * 4 + r, j = tx * 4 + c;
                const int idx = ((i >> 4) - (j >> 4) + 3) * 49
                              + (((i >> 2) & 3) - ((j >> 2) & 3) + 3) * 7
                              + ((i & 3) - (j & 3) + 3);
                const float bias = __ldg(&bt[idx * 6 + h]);
                const float mv = (grp[i] == grp[j]) ? 0.f : -100.f;
                ss[i * 65 + j] = acc[r][c] + bias + mv;
            }
        __syncthreads();

        // softmax: row sr handled by 4 threads (16 cols each)
        float* row = &ss[sr * 65 + sg * 16];
        float mx = row[0];
#pragma unroll
        for (int c = 1; c < 16; ++c) mx = fmaxf(mx, row[c]);
        mx = fmaxf(mx, __shfl_xor_sync(0xffffffffu, mx, 1));
        mx = fmaxf(mx, __shfl_xor_sync(0xffffffffu, mx, 2));
        float sum = 0.f;
#pragma unroll
        for (int c = 0; c < 16; ++c) {
            const float e = __expf(row[c] - mx);
            row[c] = e; sum += e;
        }
        sum += __shfl_xor_sync(0xffffffffu, sum, 1);
        sum += __shfl_xor_sync(0xffffffffu, sum, 2);
        const float rinv = 1.f / sum;
#pragma unroll
        for (int c = 0; c < 16; ++c) row[c] *= rinv;
        __syncthreads();

        // O = P @ V ; thread: row sr, dims sg*8..sg*8+7
        float o[8];
#pragma unroll
        for (int e = 0; e < 8; ++e) o[e] = 0.f;
#pragma unroll 8
        for (int j = 0; j < 64; ++j) {
            const float p = ss[sr * 65 + j];
            const float4 va = *(const float4*)&vs[j * 32 + sg * 8];
            const float4 vb = *(const float4*)&vs[j * 32 + sg * 8 + 4];
            o[0] = fmaf(p, va.x, o[0]); o[1] = fmaf(p, va.y, o[1]);
            o[2] = fmaf(p, va.z, o[2]); o[3] = fmaf(p, va.w, o[3]);
            o[4] = fmaf(p, vb.x, o[4]); o[5] = fmaf(p, vb.y, o[5]);
            o[6] = fmaf(p, vb.z, o[6]); o[7] = fmaf(p, vb.w, o[7]);
        }
        float* op = out + ((size_t)wid * 64 + sr) * 192 + h * 32 + sg * 8;
        *(float4*)op       = make_float4(o[0], o[1], o[2], o[3]);
        *(float4*)(op + 4) = make_float4(o[4], o[5], o[6], o[7]);
        __syncthreads();
    }
}

// ---------------- launch --------------------------------------------------------
extern "C" void kernel_launch(void* const* d_in, const int* in_sizes, int n_in,
                              void* d_out, int out_size)
{
    const float* x    = (const float*)d_in[0];
    const float* g1   = (const float*)d_in[1];
    const float* b1   = (const float*)d_in[2];
    const float* wqkv = (const float*)d_in[3];
    const float* bqkv = (const float*)d_in[4];
    const float* wo   = (const float*)d_in[5];
    const float* bo   = (const float*)d_in[6];
    const float* bt   = (const float*)d_in[7];
    const float* g2   = (const float*)d_in[8];
    const float* b2   = (const float*)d_in[9];
    const float* w1   = (const float*)d_in[10];
    const float* bm1  = (const float*)d_in[11];
    const float* w2   = (const float*)d_in[12];
    const float* bm2  = (const float*)d_in[13];
    float* out = (float*)d_out;

    float *p_xw, *p_qkv, *p_attn, *p_xo, *p_xn2, *p_h1;
    cudaGetSymbolAddress((void**)&p_xw,   g_xw);
    cudaGetSymbolAddress((void**)&p_qkv,  g_qkv);
    cudaGetSymbolAddress((void**)&p_attn, g_attn);
    cudaGetSymbolAddress((void**)&p_xo,   g_xo);
    cudaGetSymbolAddress((void**)&p_xn2,  g_xn2);
    cudaGetSymbolAddress((void**)&p_h1,   g_h1);

    // 1) LN1 + cyclic shift + window partition
    ln_kernel<true><<<NTOK / 8, 256>>>(x, g1, b1, p_xw);
    // 2) qkv = xw @ wqkv + bqkv
    gemm_kernel<0><<<dim3(576 / 64, NTOK / 128), 256>>>(p_xw, wqkv, bqkv, p_qkv,
                                                        NTOK, 576, 192, nullptr);
    // 3) windowed attention (bias + shift mask + softmax)
    attn_kernel<<<1024, 256>>>(p_qkv, bt, p_attn);
    // 4) proj + window reverse + roll back + residual -> xo
    gemm_kernel<2><<<dim3(192 / 64, NTOK / 128), 256>>>(p_attn, wo, bo, p_xo,
                                                        NTOK, 192, 192, x);
    // 5) LN2
    ln_kernel<false><<<NTOK / 8, 256>>>(p_xo, g2, b2, p_xn2);
    // 6) h1 = gelu(xn2 @ w1 + bm1)
    gemm_kernel<1><<<dim3(768 / 64, NTOK / 128), 256>>>(p_xn2, w1, bm1, p_h1,
                                                        NTOK, 768, 192, nullptr);
    // 7) out = xo + h1 @ w2 + bm2
    gemm_kernel<3><<<dim3(192 / 64, NTOK / 128), 256>>>(p_h1, w2, bm2, out,
                                                        NTOK, 192, 768, p_xo);
}

// round 4
// speedup vs baseline: 1.9794x; 1.9794x over previous
#include <cuda_runtime.h>
#include <cuda_bf16.h>
#include <math.h>
#include <stdint.h>

// ---------------- problem constants ----------------
#define NTOK 65536
#define CDIM 192

// ---------------- scratch ----------------
__device__ float g_xw  [(size_t)NTOK * 192];
__device__ float g_qkv [(size_t)NTOK * 576];
__device__ float g_attn[(size_t)NTOK * 192];
__device__ float g_xo  [(size_t)NTOK * 192];
__device__ float g_xn2 [(size_t)NTOK * 192];
__device__ float g_h1  [(size_t)NTOK * 768];

// ---------------- helpers ----------------
__device__ __forceinline__ uint32_t smem_u32(const void* p) {
    uint32_t a;
    asm("{ .reg .u64 t; cvta.to.shared.u64 t, %1; cvt.u32.u64 %0, t; }" : "=r"(a) : "l"(p));
    return a;
}
__device__ __forceinline__ void ldsm_x4(uint32_t* r, uint32_t addr) {
    asm volatile("ldmatrix.sync.aligned.m8n8.x4.shared.b16 {%0,%1,%2,%3}, [%4];"
                 : "=r"(r[0]), "=r"(r[1]), "=r"(r[2]), "=r"(r[3]) : "r"(addr));
}
__device__ __forceinline__ void mma_bf16(float* c, const uint32_t* a,
                                         uint32_t b0, uint32_t b1) {
    asm volatile(
        "mma.sync.aligned.m16n8k16.row.col.f32.bf16.bf16.f32 "
        "{%0,%1,%2,%3}, {%4,%5,%6,%7}, {%8,%9}, {%0,%1,%2,%3};"
        : "+f"(c[0]), "+f"(c[1]), "+f"(c[2]), "+f"(c[3])
        : "r"(a[0]), "r"(a[1]), "r"(a[2]), "r"(a[3]), "r"(b0), "r"(b1));
}
// pack (x -> low half, y -> high half)
__device__ __forceinline__ uint32_t pack_bf16(float x, float y) {
    uint32_t r;
    asm("cvt.rn.bf16x2.f32 %0, %1, %2;" : "=r"(r) : "f"(y), "f"(x));
    return r;
}

// ---------------- LayerNorm (+ optional shift/window permutation) -------------
template <bool PERM>
__global__ __launch_bounds__(256)
void ln_kernel(const float* __restrict__ x, const float* __restrict__ g,
               const float* __restrict__ b, float* __restrict__ out)
{
    const int t = blockIdx.x * 8 + (threadIdx.x >> 5);
    const int lane = threadIdx.x & 31;
    size_t src;
    if (PERM) {
        const int b_ = t >> 6, n = t & 63;
        const int bb = b_ >> 9, widx = b_ & 511;
        const int hs = ((widx >> 6) << 2) + (n >> 4);
        const int ws = (((widx >> 3) & 7) << 2) + ((n >> 2) & 3);
        const int ds = ((widx & 7) << 2) + (n & 3);
        src = ((((size_t)bb * 32 + ((hs + 2) & 31)) * 32 + ((ws + 2) & 31)) * 32
               + ((ds + 2) & 31));
    } else {
        src = (size_t)t;
    }
    const float* xp = x + src * CDIM;
    float v[6];
    float s = 0.f;
#pragma unroll
    for (int r = 0; r < 6; ++r) { v[r] = xp[lane + 32 * r]; s += v[r]; }
#pragma unroll
    for (int o = 16; o > 0; o >>= 1) s += __shfl_xor_sync(0xffffffffu, s, o);
    const float mean = s * (1.f / 192.f);
    float vv = 0.f;
#pragma unroll
    for (int r = 0; r < 6; ++r) { const float d = v[r] - mean; vv += d * d; }
#pragma unroll
    for (int o = 16; o > 0; o >>= 1) vv += __shfl_xor_sync(0xffffffffu, vv, o);
    const float rstd = rsqrtf(vv * (1.f / 192.f) + 1e-5f);
    float* op = out + (size_t)t * CDIM;
#pragma unroll
    for (int r = 0; r < 6; ++r) {
        const int c = lane + 32 * r;
        op[c] = (v[r] - mean) * rstd * g[c] + b[c];
    }
}

// ---------------- bf16 tensor-core GEMM (mma.sync), BM=128 BN=64 BK=32 --------
// C[M,·] = A[M,K] @ B[K,ldb](cols n0..n0+63) + bias, epilogue EPI.
// EPI: 0 bias; 1 bias+gelu; 2 bias+window-reverse-scatter+residual(x);
//      3 bias+residual (direct rows, ldc==192)
template <int EPI>
__global__ __launch_bounds__(256)
void mma_gemm(const float* __restrict__ A, const float* __restrict__ B,
              const float* __restrict__ bias, float* __restrict__ C,
              int K, int ldb, int ldc, const float* __restrict__ resid)
{
    __shared__ __align__(16) uint8_t As[128 * 80];  // row m: 32 bf16 + 16B pad
    __shared__ __align__(16) uint8_t Bs[64 * 80];   // row n: 32 bf16 (k) + pad

    const int tid = threadIdx.x;
    const int wid = tid >> 5, lane = tid & 31;
    const int m0 = blockIdx.y << 7;
    const int n0 = blockIdx.x << 6;
    const int mw = (wid >> 1) << 5;   // warp m offset (0,32,64,96)
    const int nw = (wid & 1) << 5;    // warp n offset (0,32)

    const uint32_t as_b = smem_u32(As), bs_b = smem_u32(Bs);
    const int lrow = lane & 15, lkh = lane >> 4;

    float acc[2][4][4];
#pragma unroll
    for (int i = 0; i < 2; ++i)
#pragma unroll
        for (int j = 0; j < 4; ++j)
#pragma unroll
            for (int e = 0; e < 4; ++e) acc[i][j][e] = 0.f;

    const int ar = tid >> 3, ac = tid & 7;      // A: row, float4-col
    const int bn = tid & 63;                    // B: n within tile

    for (int kc = 0; kc < K; kc += 32) {
        // ---- gmem -> regs ----
        float4 av[4];
#pragma unroll
        for (int i = 0; i < 4; ++i) {
            const int r = ar + i * 32;
            av[i] = *(const float4*)(A + (size_t)(m0 + r) * K + kc + ac * 4);
        }
        float bv[2][4];
#pragma unroll
        for (int i = 0; i < 2; ++i) {
            const int kg = (tid >> 6) + i * 4;  // 0..7
#pragma unroll
            for (int j = 0; j < 4; ++j)
                bv[i][j] = B[(size_t)(kc + kg * 4 + j) * ldb + n0 + bn];
        }
        __syncthreads();
        // ---- regs -> smem (bf16) ----
#pragma unroll
        for (int i = 0; i < 4; ++i) {
            const int r = ar + i * 32;
            uint2 p;
            p.x = pack_bf16(av[i].x, av[i].y);
            p.y = pack_bf16(av[i].z, av[i].w);
            *(uint2*)(As + r * 80 + ac * 8) = p;
        }
#pragma unroll
        for (int i = 0; i < 2; ++i) {
            const int kg = (tid >> 6) + i * 4;
            uint2 p;
            p.x = pack_bf16(bv[i][0], bv[i][1]);
            p.y = pack_bf16(bv[i][2], bv[i][3]);
            *(uint2*)(Bs + bn * 80 + kg * 8) = p;
        }
        __syncthreads();
        // ---- tensor compute ----
#pragma unroll
        for (int kk = 0; kk < 2; ++kk) {
            uint32_t a[2][4], b[2][4];
#pragma unroll
            for (int mi = 0; mi < 2; ++mi)
                ldsm_x4(a[mi], as_b + (mw + mi * 16 + lrow) * 80 + kk * 32 + lkh * 16);
#pragma unroll
            for (int ng = 0; ng < 2; ++ng)
                ldsm_x4(b[ng], bs_b + (nw + ng * 16 + lrow) * 80 + kk * 32 + lkh * 16);
#pragma unroll
            for (int mi = 0; mi < 2; ++mi)
#pragma unroll
                for (int nj = 0; nj < 4; ++nj)
                    mma_bf16(acc[mi][nj], a[mi],
                             b[nj >> 1][nj & 1], b[nj >> 1][(nj & 1) + 2]);
        }
    }

    // ---------------- epilogue ----------------
    const int g = lane >> 2, t2 = (lane & 3) * 2;
#pragma unroll
    for (int mi = 0; mi < 2; ++mi) {
#pragma unroll
        for (int half = 0; half < 2; ++half) {
            const int m = m0 + mw + mi * 16 + g + half * 8;
            size_t dst_row, res_row = 0;
            if (EPI == 2) {
                const int b_ = m >> 6, n = m & 63;
                const int bb = b_ >> 9, widx = b_ & 511;
                const int hs = ((widx >> 6) << 2) + (n >> 4);
                const int ws = (((widx >> 3) & 7) << 2) + ((n >> 2) & 3);
                const int ds = ((widx & 7) << 2) + (n & 3);
                const size_t td = ((((size_t)bb * 32 + ((hs + 2) & 31)) * 32
                                   + ((ws + 2) & 31)) * 32 + ((ds + 2) & 31));
                dst_row = td * 192;
                res_row = td * 192;
            } else {
                dst_row = (size_t)m * ldc;
                res_row = (size_t)m * 192;
            }
#pragma unroll
            for (int nj = 0; nj < 4; ++nj) {
                const int col = n0 + nw + nj * 8 + t2;
                const float2 bv = *(const float2*)(bias + col);
                float2 o;
                o.x = acc[mi][nj][half * 2 + 0] + bv.x;
                o.y = acc[mi][nj][half * 2 + 1] + bv.y;
                if (EPI == 1) {
                    const float kk = 0.70710678118654752f;
                    o.x = 0.5f * o.x * (1.f + erff(o.x * kk));
                    o.y = 0.5f * o.y * (1.f + erff(o.y * kk));
                }
                if (EPI == 2 || EPI == 3) {
                    const float2 rv = *(const float2*)(resid + res_row + col);
                    o.x += rv.x; o.y += rv.y;
                }
                *(float2*)(C + dst_row + col) = o;
            }
        }
    }
}

// ---------------- windowed attention (SIMT, unchanged) ------------------------
__global__ __launch_bounds__(256)
void attn_kernel(const float* __restrict__ qkv, const float* __restrict__ bt,
                 float* __restrict__ out)
{
    __shared__ float qs[64 * 33];
    __shared__ float ks[64 * 33];
    __shared__ float vs[64 * 32];
    __shared__ float ss[64 * 65];
    __shared__ int   grp[64];

    const int tid = threadIdx.x;
    const int wid = blockIdx.x;
    const int widx = wid & 511;
    const int wh = widx >> 6, ww = (widx >> 3) & 7, wd = widx & 7;

    if (tid < 64) {
        const int i = tid >> 4, j = (tid >> 2) & 3, k2 = tid & 3;
        const int rh = (wh < 7) ? 0 : ((i < 2) ? 1 : 2);
        const int rw = (ww < 7) ? 0 : ((j < 2) ? 1 : 2);
        const int rd = (wd < 7) ? 0 : ((k2 < 2) ? 1 : 2);
        grp[tid] = rh * 9 + rw * 3 + rd;
    }

    const int nld = tid >> 2;
    const int d0  = (tid & 3) * 8;
    const int ti = tid >> 4, tx = tid & 15;
    const int sr = tid >> 2, sg = tid & 3;
    const size_t qrow = ((size_t)wid * 64 + nld) * 576 + d0;
    const float scl = 0.17677669529663687f;

    for (int h = 0; h < 6; ++h) {
        const float* qp = qkv + qrow + h * 32;
        const float4 q0 = *(const float4*)(qp);
        const float4 q1 = *(const float4*)(qp + 4);
        const float4 k0 = *(const float4*)(qp + 192);
        const float4 k1 = *(const float4*)(qp + 196);
        const float4 v0 = *(const float4*)(qp + 384);
        const float4 v1 = *(const float4*)(qp + 388);
        float* qd = &qs[nld * 33 + d0];
        qd[0] = q0.x * scl; qd[1] = q0.y * scl; qd[2] = q0.z * scl; qd[3] = q0.w * scl;
        qd[4] = q1.x * scl; qd[5] = q1.y * scl; qd[6] = q1.z * scl; qd[7] = q1.w * scl;
        float* kd = &ks[nld * 33 + d0];
        kd[0] = k0.x; kd[1] = k0.y; kd[2] = k0.z; kd[3] = k0.w;
        kd[4] = k1.x; kd[5] = k1.y; kd[6] = k1.z; kd[7] = k1.w;
        *(float4*)&vs[nld * 32 + d0]     = v0;
        *(float4*)&vs[nld * 32 + d0 + 4] = v1;
        __syncthreads();

        float acc[4][4];
#pragma unroll
        for (int r = 0; r < 4; ++r)
#pragma unroll
            for (int c = 0; c < 4; ++c) acc[r][c] = 0.f;
#pragma unroll 8
        for (int d = 0; d < 32; ++d) {
            float aq[4], bk[4];
#pragma unroll
            for (int r = 0; r < 4; ++r) aq[r] = qs[(ti * 4 + r) * 33 + d];
#pragma unroll
            for (int c = 0; c < 4; ++c) bk[c] = ks[(tx * 4 + c) * 33 + d];
#pragma unroll
            for (int r = 0; r < 4; ++r)
#pragma unroll
                for (int c = 0; c < 4; ++c)
                    acc[r][c] = fmaf(aq[r], bk[c], acc[r][c]);
        }
#pragma unroll
        for (int r = 0; r < 4; ++r)
#pragma unroll
            for (int c = 0; c < 4; ++c) {
                const int i = ti * 4 + r, j = tx * 4 + c;
                const int idx = ((i >> 4) - (j >> 4) + 3) * 49
                              + (((i >> 2) & 3) - ((j >> 2) & 3) + 3) * 7
                              + ((i & 3) - (j & 3) + 3);
                const float bias = __ldg(&bt[idx * 6 + h]);
                const float mv = (grp[i] == grp[j]) ? 0.f : -100.f;
                ss[i * 65 + j] = acc[r][c] + bias + mv;
            }
        __syncthreads();

        float* row = &ss[sr * 65 + sg * 16];
        float mx = row[0];
#pragma unroll
        for (int c = 1; c < 16; ++c) mx = fmaxf(mx, row[c]);
        mx = fmaxf(mx, __shfl_xor_sync(0xffffffffu, mx, 1));
        mx = fmaxf(mx, __shfl_xor_sync(0xffffffffu, mx, 2));
        float sum = 0.f;
#pragma unroll
        for (int c = 0; c < 16; ++c) {
            const float e = __expf(row[c] - mx);
            row[c] = e; sum += e;
        }
        sum += __shfl_xor_sync(0xffffffffu, sum, 1);
        sum += __shfl_xor_sync(0xffffffffu, sum, 2);
        const float rinv = 1.f / sum;
#pragma unroll
        for (int c = 0; c < 16; ++c) row[c] *= rinv;
        __syncthreads();

        float o[8];
#pragma unroll
        for (int e = 0; e < 8; ++e) o[e] = 0.f;
#pragma unroll 8
        for (int j = 0; j < 64; ++j) {
            const float p = ss[sr * 65 + j];
            const float4 va = *(const float4*)&vs[j * 32 + sg * 8];
            const float4 vb = *(const float4*)&vs[j * 32 + sg * 8 + 4];
            o[0] = fmaf(p, va.x, o[0]); o[1] = fmaf(p, va.y, o[1]);
            o[2] = fmaf(p, va.z, o[2]); o[3] = fmaf(p, va.w, o[3]);
            o[4] = fmaf(p, vb.x, o[4]); o[5] = fmaf(p, vb.y, o[5]);
            o[6] = fmaf(p, vb.z, o[6]); o[7] = fmaf(p, vb.w, o[7]);
        }
        float* op = out + ((size_t)wid * 64 + sr) * 192 + h * 32 + sg * 8;
        *(float4*)op       = make_float4(o[0], o[1], o[2], o[3]);
        *(float4*)(op + 4) = make_float4(o[4], o[5], o[6], o[7]);
        __syncthreads();
    }
}

// ---------------- launch --------------------------------------------------------
extern "C" void kernel_launch(void* const* d_in, const int* in_sizes, int n_in,
                              void* d_out, int out_size)
{
    const float* x    = (const float*)d_in[0];
    const float* g1   = (const float*)d_in[1];
    const float* b1   = (const float*)d_in[2];
    const float* wqkv = (const float*)d_in[3];
    const float* bqkv = (const float*)d_in[4];
    const float* wo   = (const float*)d_in[5];
    const float* bo   = (const float*)d_in[6];
    const float* bt   = (const float*)d_in[7];
    const float* g2   = (const float*)d_in[8];
    const float* b2   = (const float*)d_in[9];
    const float* w1   = (const float*)d_in[10];
    const float* bm1  = (const float*)d_in[11];
    const float* w2   = (const float*)d_in[12];
    const float* bm2  = (const float*)d_in[13];
    float* out = (float*)d_out;

    float *p_xw, *p_qkv, *p_attn, *p_xo, *p_xn2, *p_h1;
    cudaGetSymbolAddress((void**)&p_xw,   g_xw);
    cudaGetSymbolAddress((void**)&p_qkv,  g_qkv);
    cudaGetSymbolAddress((void**)&p_attn, g_attn);
    cudaGetSymbolAddress((void**)&p_xo,   g_xo);
    cudaGetSymbolAddress((void**)&p_xn2,  g_xn2);
    cudaGetSymbolAddress((void**)&p_h1,   g_h1);

    // 1) LN1 + cyclic shift + window partition
    ln_kernel<true><<<NTOK / 8, 256>>>(x, g1, b1, p_xw);
    // 2) qkv = xw @ wqkv + bqkv   [65536,576]
    mma_gemm<0><<<dim3(9, NTOK / 128), 256>>>(p_xw, wqkv, bqkv, p_qkv,
                                              192, 576, 576, nullptr);
    // 3) windowed attention
    attn_kernel<<<1024, 256>>>(p_qkv, bt, p_attn);
    // 4) proj + window reverse + roll + residual -> xo
    mma_gemm<2><<<dim3(3, NTOK / 128), 256>>>(p_attn, wo, bo, p_xo,
                                              192, 192, 192, x);
    // 5) LN2
    ln_kernel<false><<<NTOK / 8, 256>>>(p_xo, g2, b2, p_xn2);
    // 6) h1 = gelu(xn2 @ w1 + bm1)  [65536,768]
    mma_gemm<1><<<dim3(12, NTOK / 128), 256>>>(p_xn2, w1, bm1, p_h1,
                                               192, 768, 768, nullptr);
    // 7) out = xo + h1 @ w2 + bm2
    mma_gemm<3><<<dim3(3, NTOK / 128), 256>>>(p_h1, w2, bm2, out,
                                              768, 192, 192, p_xo);
}

// round 5
// speedup vs baseline: 2.6605x; 1.3441x over previous
#include <cuda_runtime.h>
#include <cuda_bf16.h>
#include <math.h>
#include <stdint.h>

#define NTOK 65536

// ---------------- scratch ----------------
__device__ __nv_bfloat16 g_xw  [(size_t)NTOK * 192];
__device__ __nv_bfloat16 g_qkv [(size_t)NTOK * 576];
__device__ __nv_bfloat16 g_attn[(size_t)NTOK * 192];
__device__ float         g_xo  [(size_t)NTOK * 192];
__device__ __nv_bfloat16 g_xn2 [(size_t)NTOK * 192];
__device__ __nv_bfloat16 g_h1  [(size_t)NTOK * 768];
// transposed bf16 weights [N][K]
__device__ __nv_bfloat16 g_wqkvt[576 * 192];
__device__ __nv_bfloat16 g_wot  [192 * 192];
__device__ __nv_bfloat16 g_w1t  [768 * 192];
__device__ __nv_bfloat16 g_w2t  [192 * 768];

// ---------------- helpers ----------------
__device__ __forceinline__ uint32_t smem_u32(const void* p) {
    uint32_t a;
    asm("{ .reg .u64 t; cvta.to.shared.u64 t, %1; cvt.u32.u64 %0, t; }" : "=r"(a) : "l"(p));
    return a;
}
__device__ __forceinline__ void ldsm_x4(uint32_t* r, uint32_t addr) {
    asm volatile("ldmatrix.sync.aligned.m8n8.x4.shared.b16 {%0,%1,%2,%3}, [%4];"
                 : "=r"(r[0]), "=r"(r[1]), "=r"(r[2]), "=r"(r[3]) : "r"(addr));
}
__device__ __forceinline__ void mma_bf16(float* c, const uint32_t* a,
                                         uint32_t b0, uint32_t b1) {
    asm volatile(
        "mma.sync.aligned.m16n8k16.row.col.f32.bf16.bf16.f32 "
        "{%0,%1,%2,%3}, {%4,%5,%6,%7}, {%8,%9}, {%0,%1,%2,%3};"
        : "+f"(c[0]), "+f"(c[1]), "+f"(c[2]), "+f"(c[3])
        : "r"(a[0]), "r"(a[1]), "r"(a[2]), "r"(a[3]), "r"(b0), "r"(b1));
}
__device__ __forceinline__ uint32_t pack_bf16(float x, float y) {
    uint32_t r;
    asm("cvt.rn.bf16x2.f32 %0, %1, %2;" : "=r"(r) : "f"(y), "f"(x));
    return r;
}
__device__ __forceinline__ float2 bf2f(uint32_t u) {
    __nv_bfloat162 h = *reinterpret_cast<__nv_bfloat162*>(&u);
    return __bfloat1622float2(h);
}
__device__ __forceinline__ void cpa16(uint32_t dst, const void* src) {
    asm volatile("cp.async.cg.shared.global [%0], [%1], 16;" :: "r"(dst), "l"(src));
}

// ---------------- weight convert + transpose: out[n*K+k] = bf16(in[k*N+n]) ----
__global__ void wconv(const float* __restrict__ in, __nv_bfloat16* __restrict__ out,
                      int K, int N)
{
    __shared__ float t[32][33];
    const int k0 = blockIdx.x * 32, n0 = blockIdx.y * 32;
    const int tx = threadIdx.x, ty = threadIdx.y;  // 32 x 8
#pragma unroll
    for (int i = 0; i < 32; i += 8)
        t[ty + i][tx] = in[(size_t)(k0 + ty + i) * N + n0 + tx];
    __syncthreads();
#pragma unroll
    for (int i = 0; i < 32; i += 8)
        out[(size_t)(n0 + ty + i) * K + k0 + tx] = __float2bfloat16(t[tx][ty + i]);
}

// ---------------- LayerNorm (+ optional shift/window permutation), bf16 out ---
template <bool PERM>
__global__ __launch_bounds__(256)
void ln_kernel(const float* __restrict__ x, const float* __restrict__ g,
               const float* __restrict__ b, __nv_bfloat16* __restrict__ out)
{
    const int t = blockIdx.x * 8 + (threadIdx.x >> 5);
    const int lane = threadIdx.x & 31;
    size_t src;
    if (PERM) {
        const int b_ = t >> 6, n = t & 63;
        const int bb = b_ >> 9, widx = b_ & 511;
        const int hs = ((widx >> 6) << 2) + (n >> 4);
        const int ws = (((widx >> 3) & 7) << 2) + ((n >> 2) & 3);
        const int ds = ((widx & 7) << 2) + (n & 3);
        src = ((((size_t)bb * 32 + ((hs + 2) & 31)) * 32 + ((ws + 2) & 31)) * 32
               + ((ds + 2) & 31));
    } else {
        src = (size_t)t;
    }
    const float* xp = x + src * 192;
    float v[6];
    float s = 0.f;
#pragma unroll
    for (int r = 0; r < 6; ++r) { v[r] = xp[lane + 32 * r]; s += v[r]; }
#pragma unroll
    for (int o = 16; o > 0; o >>= 1) s += __shfl_xor_sync(0xffffffffu, s, o);
    const float mean = s * (1.f / 192.f);
    float vv = 0.f;
#pragma unroll
    for (int r = 0; r < 6; ++r) { const float d = v[r] - mean; vv += d * d; }
#pragma unroll
    for (int o = 16; o > 0; o >>= 1) vv += __shfl_xor_sync(0xffffffffu, vv, o);
    const float rstd = rsqrtf(vv * (1.f / 192.f) + 1e-5f);
    __nv_bfloat16* op = out + (size_t)t * 192;
#pragma unroll
    for (int r = 0; r < 6; ++r) {
        const int c = lane + 32 * r;
        op[c] = __float2bfloat16((v[r] - mean) * rstd * g[c] + b[c]);
    }
}

// ---------------- bf16 GEMM, cp.async 3-stage, BM=128 BN=64 BK=32 -------------
// C = A[M,K](bf16) @ Bt[N,K](bf16)^T + bias. EPI: 0 bias->bf16; 1 bias+gelu->bf16;
// 2 bias+winrev-scatter+residual(x)->f32; 3 bias+residual->f32
template <int EPI>
__global__ __launch_bounds__(256)
void mma_gemm(const __nv_bfloat16* __restrict__ A, const __nv_bfloat16* __restrict__ Bt,
              const float* __restrict__ bias, void* __restrict__ Cv,
              int K, int ldc, const float* __restrict__ resid)
{
    constexpr bool OBF = (EPI == 0 || EPI == 1);
    __shared__ __align__(16) uint8_t As[3 * 128 * 80];
    __shared__ __align__(16) uint8_t Bs[3 * 64 * 80];

    const int tid = threadIdx.x;
    const int wid = tid >> 5, lane = tid & 31;
    const int m0 = blockIdx.y << 7;
    const int n0 = blockIdx.x << 6;
    const int mw = (wid >> 1) << 5;
    const int nw = (wid & 1) << 5;
    const uint32_t as_b = smem_u32(As), bs_b = smem_u32(Bs);
    const int lrow = lane & 15, lkh = lane >> 4;
    const int NC = K >> 5;

    const int ar0 = tid >> 2, aseg = tid & 3;   // + second A op at row+64
    const int br = tid >> 2, bseg = tid & 3;

    auto issue = [&](int c) {
        if (c < NC) {
            const int st = c % 3;
            const int kc = c << 5;
            const uint32_t ab = as_b + st * 10240;
            const uint32_t bb = bs_b + st * 5120;
            cpa16(ab + ar0 * 80 + aseg * 16,
                  A + (size_t)(m0 + ar0) * K + kc + aseg * 8);
            cpa16(ab + (ar0 + 64) * 80 + aseg * 16,
                  A + (size_t)(m0 + ar0 + 64) * K + kc + aseg * 8);
            cpa16(bb + br * 80 + bseg * 16,
                  Bt + (size_t)(n0 + br) * K + kc + bseg * 8);
        }
        asm volatile("cp.async.commit_group;" ::: "memory");
    };

    float acc[2][4][4];
#pragma unroll
    for (int i = 0; i < 2; ++i)
#pragma unroll
        for (int j = 0; j < 4; ++j)
#pragma unroll
            for (int e = 0; e < 4; ++e) acc[i][j][e] = 0.f;

    issue(0);
    issue(1);
    for (int c = 0; c < NC; ++c) {
        asm volatile("cp.async.wait_group 1;" ::: "memory");
        __syncthreads();
        issue(c + 2);
        const int st = c % 3;
        const uint32_t ab = as_b + st * 10240;
        const uint32_t bb = bs_b + st * 5120;
#pragma unroll
        for (int kk = 0; kk < 2; ++kk) {
            uint32_t a[2][4], b[2][4];
#pragma unroll
            for (int mi = 0; mi < 2; ++mi)
                ldsm_x4(a[mi], ab + (mw + mi * 16 + lrow) * 80 + kk * 32 + lkh * 16);
#pragma unroll
            for (int ng = 0; ng < 2; ++ng)
                ldsm_x4(b[ng], bb + (nw + ng * 16 + lrow) * 80 + kk * 32 + lkh * 16);
#pragma unroll
            for (int mi = 0; mi < 2; ++mi)
#pragma unroll
                for (int nj = 0; nj < 4; ++nj)
                    mma_bf16(acc[mi][nj], a[mi],
                             b[nj >> 1][nj & 1], b[nj >> 1][(nj & 1) + 2]);
        }
    }

    // ---------------- epilogue ----------------
    const int g = lane >> 2, t2 = (lane & 3) * 2;
#pragma unroll
    for (int mi = 0; mi < 2; ++mi) {
#pragma unroll
        for (int half = 0; half < 2; ++half) {
            const int m = m0 + mw + mi * 16 + g + half * 8;
            size_t dst_row, res_row = 0;
            if (EPI == 2) {
                const int b_ = m >> 6, n = m & 63;
                const int bb2 = b_ >> 9, widx = b_ & 511;
                const int hs = ((widx >> 6) << 2) + (n >> 4);
                const int ws = (((widx >> 3) & 7) << 2) + ((n >> 2) & 3);
                const int ds = ((widx & 7) << 2) + (n & 3);
                const size_t td = ((((size_t)bb2 * 32 + ((hs + 2) & 31)) * 32
                                   + ((ws + 2) & 31)) * 32 + ((ds + 2) & 31));
                dst_row = td * 192;
                res_row = td * 192;
            } else {
                dst_row = (size_t)m * ldc;
                res_row = (size_t)m * 192;
            }
#pragma unroll
            for (int nj = 0; nj < 4; ++nj) {
                const int col = n0 + nw + nj * 8 + t2;
                const float2 bv = *(const float2*)(bias + col);
                float2 o;
                o.x = acc[mi][nj][half * 2 + 0] + bv.x;
                o.y = acc[mi][nj][half * 2 + 1] + bv.y;
                if (EPI == 1) {
                    const float kk = 0.70710678118654752f;
                    o.x = 0.5f * o.x * (1.f + erff(o.x * kk));
                    o.y = 0.5f * o.y * (1.f + erff(o.y * kk));
                }
                if (EPI == 2 || EPI == 3) {
                    const float2 rv = *(const float2*)(resid + res_row + col);
                    o.x += rv.x; o.y += rv.y;
                }
                if (OBF) {
                    *(uint32_t*)((__nv_bfloat16*)Cv + dst_row + col) = pack_bf16(o.x, o.y);
                } else {
                    *(float2*)((float*)Cv + dst_row + col) = o;
                }
            }
        }
    }
}

// ---------------- windowed attention (bf16 in/out, fp32 math) -----------------
__global__ __launch_bounds__(256)
void attn_kernel(const __nv_bfloat16* __restrict__ qkv, const float* __restrict__ bt,
                 __nv_bfloat16* __restrict__ out)
{
    __shared__ float qs[64 * 33];
    __shared__ float ks[64 * 33];
    __shared__ float vs[64 * 32];
    __shared__ float ss[64 * 65];
    __shared__ int   grp[64];

    const int tid = threadIdx.x;
    const int wid = blockIdx.x;
    const int widx = wid & 511;
    const int wh = widx >> 6, ww = (widx >> 3) & 7, wd = widx & 7;

    if (tid < 64) {
        const int i = tid >> 4, j = (tid >> 2) & 3, k2 = tid & 3;
        const int rh = (wh < 7) ? 0 : ((i < 2) ? 1 : 2);
        const int rw = (ww < 7) ? 0 : ((j < 2) ? 1 : 2);
        const int rd = (wd < 7) ? 0 : ((k2 < 2) ? 1 : 2);
        grp[tid] = rh * 9 + rw * 3 + rd;
    }

    const int nld = tid >> 2;
    const int d0  = (tid & 3) * 8;
    const int ti = tid >> 4, tx = tid & 15;
    const int sr = tid >> 2, sg = tid & 3;
    const size_t qrow = ((size_t)wid * 64 + nld) * 576 + d0;
    const float scl = 0.17677669529663687f;

    for (int h = 0; h < 6; ++h) {
        const __nv_bfloat16* qp = qkv + qrow + h * 32;
        const uint4 qu = *(const uint4*)(qp);
        const uint4 ku = *(const uint4*)(qp + 192);
        const uint4 vu = *(const uint4*)(qp + 384);
        const float2 q0 = bf2f(qu.x), q1 = bf2f(qu.y), q2 = bf2f(qu.z), q3 = bf2f(qu.w);
        const float2 k0 = bf2f(ku.x), k1 = bf2f(ku.y), k2 = bf2f(ku.z), k3 = bf2f(ku.w);
        const float2 v0 = bf2f(vu.x), v1 = bf2f(vu.y), v2 = bf2f(vu.z), v3 = bf2f(vu.w);
        float* qd = &qs[nld * 33 + d0];
        qd[0] = q0.x * scl; qd[1] = q0.y * scl; qd[2] = q1.x * scl; qd[3] = q1.y * scl;
        qd[4] = q2.x * scl; qd[5] = q2.y * scl; qd[6] = q3.x * scl; qd[7] = q3.y * scl;
        float* kd = &ks[nld * 33 + d0];
        kd[0] = k0.x; kd[1] = k0.y; kd[2] = k1.x; kd[3] = k1.y;
        kd[4] = k2.x; kd[5] = k2.y; kd[6] = k3.x; kd[7] = k3.y;
        float* vd = &vs[nld * 32 + d0];
        vd[0] = v0.x; vd[1] = v0.y; vd[2] = v1.x; vd[3] = v1.y;
        vd[4] = v2.x; vd[5] = v2.y; vd[6] = v3.x; vd[7] = v3.y;
        __syncthreads();

        float acc[4][4];
#pragma unroll
        for (int r = 0; r < 4; ++r)
#pragma unroll
            for (int c = 0; c < 4; ++c) acc[r][c] = 0.f;
#pragma unroll 8
        for (int d = 0; d < 32; ++d) {
            float aq[4], bk[4];
#pragma unroll
            for (int r = 0; r < 4; ++r) aq[r] = qs[(ti * 4 + r) * 33 + d];
#pragma unroll
            for (int c = 0; c < 4; ++c) bk[c] = ks[(tx * 4 + c) * 33 + d];
#pragma unroll
            for (int r = 0; r < 4; ++r)
#pragma unroll
                for (int c = 0; c < 4; ++c)
                    acc[r][c] = fmaf(aq[r], bk[c], acc[r][c]);
        }
#pragma unroll
        for (int r = 0; r < 4; ++r)
#pragma unroll
            for (int c = 0; c < 4; ++c) {
                const int i = ti * 4 + r, j = tx * 4 + c;
                const int idx = ((i >> 4) - (j >> 4) + 3) * 49
                              + (((i >> 2) & 3) - ((j >> 2) & 3) + 3) * 7
                              + ((i & 3) - (j & 3) + 3);
                const float bias = __ldg(&bt[idx * 6 + h]);
                const float mv = (grp[i] == grp[j]) ? 0.f : -100.f;
                ss[i * 65 + j] = acc[r][c] + bias + mv;
            }
        __syncthreads();

        float* row = &ss[sr * 65 + sg * 16];
        float mx = row[0];
#pragma unroll
        for (int c = 1; c < 16; ++c) mx = fmaxf(mx, row[c]);
        mx = fmaxf(mx, __shfl_xor_sync(0xffffffffu, mx, 1));
        mx = fmaxf(mx, __shfl_xor_sync(0xffffffffu, mx, 2));
        float sum = 0.f;
#pragma unroll
        for (int c = 0; c < 16; ++c) {
            const float e = __expf(row[c] - mx);
            row[c] = e; sum += e;
        }
        sum += __shfl_xor_sync(0xffffffffu, sum, 1);
        sum += __shfl_xor_sync(0xffffffffu, sum, 2);
        const float rinv = 1.f / sum;
#pragma unroll
        for (int c = 0; c < 16; ++c) row[c] *= rinv;
        __syncthreads();

        float o[8];
#pragma unroll
        for (int e = 0; e < 8; ++e) o[e] = 0.f;
#pragma unroll 8
        for (int j = 0; j < 64; ++j) {
            const float p = ss[sr * 65 + j];
            const float4 va = *(const float4*)&vs[j * 32 + sg * 8];
            const float4 vb = *(const float4*)&vs[j * 32 + sg * 8 + 4];
            o[0] = fmaf(p, va.x, o[0]); o[1] = fmaf(p, va.y, o[1]);
            o[2] = fmaf(p, va.z, o[2]); o[3] = fmaf(p, va.w, o[3]);
            o[4] = fmaf(p, vb.x, o[4]); o[5] = fmaf(p, vb.y, o[5]);
            o[6] = fmaf(p, vb.z, o[6]); o[7] = fmaf(p, vb.w, o[7]);
        }
        __nv_bfloat16* op = out + ((size_t)wid * 64 + sr) * 192 + h * 32 + sg * 8;
        uint4 ov;
        ov.x = pack_bf16(o[0], o[1]); ov.y = pack_bf16(o[2], o[3]);
        ov.z = pack_bf16(o[4], o[5]); ov.w = pack_bf16(o[6], o[7]);
        *(uint4*)op = ov;
        __syncthreads();
    }
}

// ---------------- launch --------------------------------------------------------
extern "C" void kernel_launch(void* const* d_in, const int* in_sizes, int n_in,
                              void* d_out, int out_size)
{
    const float* x    = (const float*)d_in[0];
    const float* g1   = (const float*)d_in[1];
    const float* b1   = (const float*)d_in[2];
    const float* wqkv = (const float*)d_in[3];
    const float* bqkv = (const float*)d_in[4];
    const float* wo   = (const float*)d_in[5];
    const float* bo   = (const float*)d_in[6];
    const float* bt   = (const float*)d_in[7];
    const float* g2   = (const float*)d_in[8];
    const float* b2   = (const float*)d_in[9];
    const float* w1   = (const float*)d_in[10];
    const float* bm1  = (const float*)d_in[11];
    const float* w2   = (const float*)d_in[12];
    const float* bm2  = (const float*)d_in[13];
    float* out = (float*)d_out;

    __nv_bfloat16 *p_xw, *p_qkv, *p_attn, *p_xn2, *p_h1;
    __nv_bfloat16 *p_wqkvt, *p_wot, *p_w1t, *p_w2t;
    float *p_xo;
    cudaGetSymbolAddress((void**)&p_xw,    g_xw);
    cudaGetSymbolAddress((void**)&p_qkv,   g_qkv);
    cudaGetSymbolAddress((void**)&p_attn,  g_attn);
    cudaGetSymbolAddress((void**)&p_xo,    g_xo);
    cudaGetSymbolAddress((void**)&p_xn2,   g_xn2);
    cudaGetSymbolAddress((void**)&p_h1,    g_h1);
    cudaGetSymbolAddress((void**)&p_wqkvt, g_wqkvt);
    cudaGetSymbolAddress((void**)&p_wot,   g_wot);
    cudaGetSymbolAddress((void**)&p_w1t,   g_w1t);
    cudaGetSymbolAddress((void**)&p_w2t,   g_w2t);

    dim3 wb(32, 8);
    wconv<<<dim3(6, 18),  wb>>>(wqkv, p_wqkvt, 192, 576);
    wconv<<<dim3(6, 6),   wb>>>(wo,   p_wot,   192, 192);
    wconv<<<dim3(6, 24),  wb>>>(w1,   p_w1t,   192, 768);
    wconv<<<dim3(24, 6),  wb>>>(w2,   p_w2t,   768, 192);

    // 1) LN1 + shift + window partition (bf16)
    ln_kernel<true><<<NTOK / 8, 256>>>(x, g1, b1, p_xw);
    // 2) qkv
    mma_gemm<0><<<dim3(9, NTOK / 128), 256>>>(p_xw, p_wqkvt, bqkv, p_qkv,
                                              192, 576, nullptr);
    // 3) attention
    attn_kernel<<<1024, 256>>>(p_qkv, bt, p_attn);
    // 4) proj + window reverse + roll + residual -> xo (fp32)
    mma_gemm<2><<<dim3(3, NTOK / 128), 256>>>(p_attn, p_wot, bo, p_xo,
                                              192, 192, x);
    // 5) LN2 (bf16)
    ln_kernel<false><<<NTOK / 8, 256>>>(p_xo, g2, b2, p_xn2);
    // 6) h1 = gelu(xn2 @ w1 + bm1) (bf16)
    mma_gemm<1><<<dim3(12, NTOK / 128), 256>>>(p_xn2, p_w1t, bm1, p_h1,
                                               192, 768, nullptr);
    // 7) out = xo + h1 @ w2 + bm2 (fp32)
    mma_gemm<3><<<dim3(3, NTOK / 128), 256>>>(p_h1, p_w2t, bm2, out,
                                              768, 192, p_xo);
}

// round 6
// speedup vs baseline: 3.5008x; 1.3159x over previous
#include <cuda_runtime.h>
#include <cuda_bf16.h>
#include <math.h>
#include <stdint.h>

#define NTOK 65536

// ---------------- scratch ----------------
__device__ __nv_bfloat16 g_xw  [(size_t)NTOK * 192];
__device__ __nv_bfloat16 g_qkv [(size_t)NTOK * 576];
__device__ __nv_bfloat16 g_attn[(size_t)NTOK * 192];
__device__ float         g_xo  [(size_t)NTOK * 192];
__device__ __nv_bfloat16 g_xn2 [(size_t)NTOK * 192];
__device__ __nv_bfloat16 g_h1  [(size_t)NTOK * 768];
__device__ __nv_bfloat16 g_wqkvt[576 * 192];
__device__ __nv_bfloat16 g_wot  [192 * 192];
__device__ __nv_bfloat16 g_w1t  [768 * 192];
__device__ __nv_bfloat16 g_w2t  [192 * 768];

// ---------------- helpers ----------------
__device__ __forceinline__ uint32_t smem_u32(const void* p) {
    uint32_t a;
    asm("{ .reg .u64 t; cvta.to.shared.u64 t, %1; cvt.u32.u64 %0, t; }" : "=r"(a) : "l"(p));
    return a;
}
__device__ __forceinline__ void ldsm_x4(uint32_t* r, uint32_t addr) {
    asm volatile("ldmatrix.sync.aligned.m8n8.x4.shared.b16 {%0,%1,%2,%3}, [%4];"
                 : "=r"(r[0]), "=r"(r[1]), "=r"(r[2]), "=r"(r[3]) : "r"(addr));
}
__device__ __forceinline__ void ldsm_x4t(uint32_t* r, uint32_t addr) {
    asm volatile("ldmatrix.sync.aligned.m8n8.x4.trans.shared.b16 {%0,%1,%2,%3}, [%4];"
                 : "=r"(r[0]), "=r"(r[1]), "=r"(r[2]), "=r"(r[3]) : "r"(addr));
}
__device__ __forceinline__ void mma_bf16(float* c, const uint32_t* a,
                                         uint32_t b0, uint32_t b1) {
    asm volatile(
        "mma.sync.aligned.m16n8k16.row.col.f32.bf16.bf16.f32 "
        "{%0,%1,%2,%3}, {%4,%5,%6,%7}, {%8,%9}, {%0,%1,%2,%3};"
        : "+f"(c[0]), "+f"(c[1]), "+f"(c[2]), "+f"(c[3])
        : "r"(a[0]), "r"(a[1]), "r"(a[2]), "r"(a[3]), "r"(b0), "r"(b1));
}
__device__ __forceinline__ uint32_t pack_bf16(float x, float y) {
    uint32_t r;
    asm("cvt.rn.bf16x2.f32 %0, %1, %2;" : "=r"(r) : "f"(y), "f"(x));
    return r;
}
__device__ __forceinline__ void cpa16(uint32_t dst, const void* src) {
    asm volatile("cp.async.cg.shared.global [%0], [%1], 16;" :: "r"(dst), "l"(src));
}

// ---------------- weight convert + transpose ----------------------------------
__global__ void wconv(const float* __restrict__ in, __nv_bfloat16* __restrict__ out,
                      int K, int N)
{
    __shared__ float t[32][33];
    const int k0 = blockIdx.x * 32, n0 = blockIdx.y * 32;
    const int tx = threadIdx.x, ty = threadIdx.y;
#pragma unroll
    for (int i = 0; i < 32; i += 8)
        t[ty + i][tx] = in[(size_t)(k0 + ty + i) * N + n0 + tx];
    __syncthreads();
#pragma unroll
    for (int i = 0; i < 32; i += 8)
        out[(size_t)(n0 + ty + i) * K + k0 + tx] = __float2bfloat16(t[tx][ty + i]);
}

// ---------------- LayerNorm ----------------------------------------------------
template <bool PERM>
__global__ __launch_bounds__(256)
void ln_kernel(const float* __restrict__ x, const float* __restrict__ g,
               const float* __restrict__ b, __nv_bfloat16* __restrict__ out)
{
    const int t = blockIdx.x * 8 + (threadIdx.x >> 5);
    const int lane = threadIdx.x & 31;
    size_t src;
    if (PERM) {
        const int b_ = t >> 6, n = t & 63;
        const int bb = b_ >> 9, widx = b_ & 511;
        const int hs = ((widx >> 6) << 2) + (n >> 4);
        const int ws = (((widx >> 3) & 7) << 2) + ((n >> 2) & 3);
        const int ds = ((widx & 7) << 2) + (n & 3);
        src = ((((size_t)bb * 32 + ((hs + 2) & 31)) * 32 + ((ws + 2) & 31)) * 32
               + ((ds + 2) & 31));
    } else {
        src = (size_t)t;
    }
    const float* xp = x + src * 192;
    float v[6];
    float s = 0.f;
#pragma unroll
    for (int r = 0; r < 6; ++r) { v[r] = xp[lane + 32 * r]; s += v[r]; }
#pragma unroll
    for (int o = 16; o > 0; o >>= 1) s += __shfl_xor_sync(0xffffffffu, s, o);
    const float mean = s * (1.f / 192.f);
    float vv = 0.f;
#pragma unroll
    for (int r = 0; r < 6; ++r) { const float d = v[r] - mean; vv += d * d; }
#pragma unroll
    for (int o = 16; o > 0; o >>= 1) vv += __shfl_xor_sync(0xffffffffu, vv, o);
    const float rstd = rsqrtf(vv * (1.f / 192.f) + 1e-5f);
    __nv_bfloat16* op = out + (size_t)t * 192;
#pragma unroll
    for (int r = 0; r < 6; ++r) {
        const int c = lane + 32 * r;
        op[c] = __float2bfloat16((v[r] - mean) * rstd * g[c] + b[c]);
    }
}

// ---------------- bf16 GEMM, cp.async 3-stage, BM=128 BN=64 BK=32 -------------
template <int EPI>
__global__ __launch_bounds__(256)
void mma_gemm(const __nv_bfloat16* __restrict__ A, const __nv_bfloat16* __restrict__ Bt,
              const float* __restrict__ bias, void* __restrict__ Cv,
              int K, int ldc, const float* __restrict__ resid)
{
    constexpr bool OBF = (EPI == 0 || EPI == 1);
    __shared__ __align__(16) uint8_t As[3 * 128 * 80];
    __shared__ __align__(16) uint8_t Bs[3 * 64 * 80];

    const int tid = threadIdx.x;
    const int wid = tid >> 5, lane = tid & 31;
    const int m0 = blockIdx.y << 7;
    const int n0 = blockIdx.x << 6;
    const int mw = (wid >> 1) << 5;
    const int nw = (wid & 1) << 5;
    const uint32_t as_b = smem_u32(As), bs_b = smem_u32(Bs);
    const int lrow = lane & 15, lkh = lane >> 4;
    const int NC = K >> 5;

    const int ar0 = tid >> 2, aseg = tid & 3;
    const int br = tid >> 2, bseg = tid & 3;

    auto issue = [&](int c) {
        if (c < NC) {
            const int st = c % 3;
            const int kc = c << 5;
            const uint32_t ab = as_b + st * 10240;
            const uint32_t bb = bs_b + st * 5120;
            cpa16(ab + ar0 * 80 + aseg * 16,
                  A + (size_t)(m0 + ar0) * K + kc + aseg * 8);
            cpa16(ab + (ar0 + 64) * 80 + aseg * 16,
                  A + (size_t)(m0 + ar0 + 64) * K + kc + aseg * 8);
            cpa16(bb + br * 80 + bseg * 16,
                  Bt + (size_t)(n0 + br) * K + kc + bseg * 8);
        }
        asm volatile("cp.async.commit_group;" ::: "memory");
    };

    float acc[2][4][4];
#pragma unroll
    for (int i = 0; i < 2; ++i)
#pragma unroll
        for (int j = 0; j < 4; ++j)
#pragma unroll
            for (int e = 0; e < 4; ++e) acc[i][j][e] = 0.f;

    issue(0);
    issue(1);
    for (int c = 0; c < NC; ++c) {
        asm volatile("cp.async.wait_group 1;" ::: "memory");
        __syncthreads();
        issue(c + 2);
        const int st = c % 3;
        const uint32_t ab = as_b + st * 10240;
        const uint32_t bb = bs_b + st * 5120;
#pragma unroll
        for (int kk = 0; kk < 2; ++kk) {
            uint32_t a[2][4], b[2][4];
#pragma unroll
            for (int mi = 0; mi < 2; ++mi)
                ldsm_x4(a[mi], ab + (mw + mi * 16 + lrow) * 80 + kk * 32 + lkh * 16);
#pragma unroll
            for (int ng = 0; ng < 2; ++ng)
                ldsm_x4(b[ng], bb + (nw + ng * 16 + lrow) * 80 + kk * 32 + lkh * 16);
#pragma unroll
            for (int mi = 0; mi < 2; ++mi)
#pragma unroll
                for (int nj = 0; nj < 4; ++nj)
                    mma_bf16(acc[mi][nj], a[mi],
                             b[nj >> 1][nj & 1], b[nj >> 1][(nj & 1) + 2]);
        }
    }

    const int g = lane >> 2, t2 = (lane & 3) * 2;
#pragma unroll
    for (int mi = 0; mi < 2; ++mi) {
#pragma unroll
        for (int half = 0; half < 2; ++half) {
            const int m = m0 + mw + mi * 16 + g + half * 8;
            size_t dst_row, res_row = 0;
            if (EPI == 2) {
                const int b_ = m >> 6, n = m & 63;
                const int bb2 = b_ >> 9, widx = b_ & 511;
                const int hs = ((widx >> 6) << 2) + (n >> 4);
                const int ws = (((widx >> 3) & 7) << 2) + ((n >> 2) & 3);
                const int ds = ((widx & 7) << 2) + (n & 3);
                const size_t td = ((((size_t)bb2 * 32 + ((hs + 2) & 31)) * 32
                                   + ((ws + 2) & 31)) * 32 + ((ds + 2) & 31));
                dst_row = td * 192;
                res_row = td * 192;
            } else {
                dst_row = (size_t)m * ldc;
                res_row = (size_t)m * 192;
            }
#pragma unroll
            for (int nj = 0; nj < 4; ++nj) {
                const int col = n0 + nw + nj * 8 + t2;
                const float2 bv = *(const float2*)(bias + col);
                float2 o;
                o.x = acc[mi][nj][half * 2 + 0] + bv.x;
                o.y = acc[mi][nj][half * 2 + 1] + bv.y;
                if (EPI == 1) {
                    const float kk = 0.70710678118654752f;
                    o.x = 0.5f * o.x * (1.f + erff(o.x * kk));
                    o.y = 0.5f * o.y * (1.f + erff(o.y * kk));
                }
                if (EPI == 2 || EPI == 3) {
                    const float2 rv = *(const float2*)(resid + res_row + col);
                    o.x += rv.x; o.y += rv.y;
                }
                if (OBF) {
                    *(uint32_t*)((__nv_bfloat16*)Cv + dst_row + col) = pack_bf16(o.x, o.y);
                } else {
                    *(float2*)((float*)Cv + dst_row + col) = o;
                }
            }
        }
    }
}

// ---------------- windowed attention (tensor-core bf16) -----------------------
// One CTA per window; per head: QK^T via mma, softmax SIMT fp32, PV via mma.
__global__ __launch_bounds__(256)
void attn_kernel(const __nv_bfloat16* __restrict__ qkv, const float* __restrict__ bt,
                 __nv_bfloat16* __restrict__ out)
{
    __shared__ __align__(16) uint8_t qs[64 * 80];
    __shared__ __align__(16) uint8_t ks[64 * 80];
    __shared__ __align__(16) uint8_t vs[64 * 80];
    __shared__ __align__(16) uint8_t ps[64 * 144];
    __shared__ float ss[64 * 65];
    __shared__ int   grp[64];

    const int tid = threadIdx.x;
    const int wnd = blockIdx.x;
    const int widx = wnd & 511;
    const int wh = widx >> 6, ww = (widx >> 3) & 7, wd = widx & 7;

    if (tid < 64) {
        const int i = tid >> 4, j = (tid >> 2) & 3, k2 = tid & 3;
        const int rh = (wh < 7) ? 0 : ((i < 2) ? 1 : 2);
        const int rw = (ww < 7) ? 0 : ((j < 2) ? 1 : 2);
        const int rd = (wd < 7) ? 0 : ((k2 < 2) ? 1 : 2);
        grp[tid] = rh * 9 + rw * 3 + rd;
    }

    const int warp = tid >> 5, lane = tid & 31;
    const int lrow = lane & 15, lkh = lane >> 4;
    const int g = lane >> 2, t2 = (lane & 3) * 2;
    const int row = tid >> 2, seg = tid & 3;
    const int sr = tid >> 2, sg = tid & 3;
    const uint32_t qs_b = smem_u32(qs), ks_b = smem_u32(ks);
    const uint32_t vs_b = smem_u32(vs), ps_b = smem_u32(ps);
    const size_t base = ((size_t)wnd * 64 + row) * 576 + seg * 8;
    const float scl = 0.17677669529663687f; // 1/sqrt(32)

    const int msl = (warp & 3) * 16;   // m slab for this warp
    const int nh  = (warp >> 2) * 32;  // score n-half
    const int dh  = (warp >> 2) * 16;  // PV d-half

    for (int h = 0; h < 6; ++h) {
        // ---- load q,k,v (bf16, 16B per thread each) ----
        const __nv_bfloat16* qp = qkv + base + h * 32;
        const uint4 qu = *(const uint4*)(qp);
        const uint4 ku = *(const uint4*)(qp + 192);
        const uint4 vu = *(const uint4*)(qp + 384);
        *(uint4*)(qs + row * 80 + seg * 16) = qu;
        *(uint4*)(ks + row * 80 + seg * 16) = ku;
        *(uint4*)(vs + row * 80 + seg * 16) = vu;
        __syncthreads();

        // ---- scores: warp = rows msl..msl+16, cols nh..nh+32 ----
        float acc[4][4];
#pragma unroll
        for (int nj = 0; nj < 4; ++nj)
#pragma unroll
            for (int e = 0; e < 4; ++e) acc[nj][e] = 0.f;
#pragma unroll
        for (int kk = 0; kk < 2; ++kk) {
            uint32_t a[4], b[2][4];
            ldsm_x4(a, qs_b + (msl + lrow) * 80 + kk * 32 + lkh * 16);
#pragma unroll
            for (int ng = 0; ng < 2; ++ng)
                ldsm_x4(b[ng], ks_b + (nh + ng * 16 + lrow) * 80 + kk * 32 + lkh * 16);
#pragma unroll
            for (int nj = 0; nj < 4; ++nj)
                mma_bf16(acc[nj], a, b[nj >> 1][nj & 1], b[nj >> 1][(nj & 1) + 2]);
        }
        // bias + mask + scale -> ss (fp32)
#pragma unroll
        for (int nj = 0; nj < 4; ++nj)
#pragma unroll
            for (int e = 0; e < 4; ++e) {
                const int i = msl + g + (e >> 1) * 8;
                const int j = nh + nj * 8 + t2 + (e & 1);
                const int idx = ((i >> 4) - (j >> 4) + 3) * 49
                              + (((i >> 2) & 3) - ((j >> 2) & 3) + 3) * 7
                              + ((i & 3) - (j & 3) + 3);
                const float bias = __ldg(&bt[idx * 6 + h]);
                const float mv = (grp[i] == grp[j]) ? 0.f : -100.f;
                ss[i * 65 + j] = acc[nj][e] * scl + bias + mv;
            }
        __syncthreads();

        // ---- softmax: row sr, 4 threads x 16 cols ----
        float* rowp = &ss[sr * 65 + sg * 16];
        float mx = rowp[0];
#pragma unroll
        for (int c = 1; c < 16; ++c) mx = fmaxf(mx, rowp[c]);
        mx = fmaxf(mx, __shfl_xor_sync(0xffffffffu, mx, 1));
        mx = fmaxf(mx, __shfl_xor_sync(0xffffffffu, mx, 2));
        float sum = 0.f;
        float ev[16];
#pragma unroll
        for (int c = 0; c < 16; ++c) { ev[c] = __expf(rowp[c] - mx); sum += ev[c]; }
        sum += __shfl_xor_sync(0xffffffffu, sum, 1);
        sum += __shfl_xor_sync(0xffffffffu, sum, 2);
        const float rinv = 1.f / sum;
        // convert P to bf16 into ps (same cells this thread owns)
        uint32_t pk[8];
#pragma unroll
        for (int c = 0; c < 8; ++c)
            pk[c] = pack_bf16(ev[2 * c] * rinv, ev[2 * c + 1] * rinv);
        *(uint4*)(ps + sr * 144 + sg * 32)      = make_uint4(pk[0], pk[1], pk[2], pk[3]);
        *(uint4*)(ps + sr * 144 + sg * 32 + 16) = make_uint4(pk[4], pk[5], pk[6], pk[7]);
        __syncthreads();

        // ---- PV: warp = rows msl..msl+16, d cols dh..dh+16 ----
        float o[2][4];
#pragma unroll
        for (int nt = 0; nt < 2; ++nt)
#pragma unroll
            for (int e = 0; e < 4; ++e) o[nt][e] = 0.f;
#pragma unroll
        for (int kc = 0; kc < 4; ++kc) {
            uint32_t a[4], b[4];
            ldsm_x4(a, ps_b + (msl + lrow) * 144 + kc * 32 + lkh * 16);
            ldsm_x4t(b, vs_b + (kc * 16 + lrow) * 80 + (dh + lkh * 8) * 2);
            mma_bf16(o[0], a, b[0], b[1]);
            mma_bf16(o[1], a, b[2], b[3]);
        }
        // store bf16 pairs
#pragma unroll
        for (int nt = 0; nt < 2; ++nt) {
            const int d = dh + nt * 8 + t2;
            __nv_bfloat16* op0 = out + ((size_t)wnd * 64 + msl + g) * 192 + h * 32 + d;
            __nv_bfloat16* op1 = op0 + 8 * 192;
            *(uint32_t*)op0 = pack_bf16(o[nt][0], o[nt][1]);
            *(uint32_t*)op1 = pack_bf16(o[nt][2], o[nt][3]);
        }
        __syncthreads();
    }
}

// ---------------- launch --------------------------------------------------------
extern "C" void kernel_launch(void* const* d_in, const int* in_sizes, int n_in,
                              void* d_out, int out_size)
{
    const float* x    = (const float*)d_in[0];
    const float* g1   = (const float*)d_in[1];
    const float* b1   = (const float*)d_in[2];
    const float* wqkv = (const float*)d_in[3];
    const float* bqkv = (const float*)d_in[4];
    const float* wo   = (const float*)d_in[5];
    const float* bo   = (const float*)d_in[6];
    const float* bt   = (const float*)d_in[7];
    const float* g2   = (const float*)d_in[8];
    const float* b2   = (const float*)d_in[9];
    const float* w1   = (const float*)d_in[10];
    const float* bm1  = (const float*)d_in[11];
    const float* w2   = (const float*)d_in[12];
    const float* bm2  = (const float*)d_in[13];
    float* out = (float*)d_out;

    __nv_bfloat16 *p_xw, *p_qkv, *p_attn, *p_xn2, *p_h1;
    __nv_bfloat16 *p_wqkvt, *p_wot, *p_w1t, *p_w2t;
    float *p_xo;
    cudaGetSymbolAddress((void**)&p_xw,    g_xw);
    cudaGetSymbolAddress((void**)&p_qkv,   g_qkv);
    cudaGetSymbolAddress((void**)&p_attn,  g_attn);
    cudaGetSymbolAddress((void**)&p_xo,    g_xo);
    cudaGetSymbolAddress((void**)&p_xn2,   g_xn2);
    cudaGetSymbolAddress((void**)&p_h1,    g_h1);
    cudaGetSymbolAddress((void**)&p_wqkvt, g_wqkvt);
    cudaGetSymbolAddress((void**)&p_wot,   g_wot);
    cudaGetSymbolAddress((void**)&p_w1t,   g_w1t);
    cudaGetSymbolAddress((void**)&p_w2t,   g_w2t);

    dim3 wb(32, 8);
    wconv<<<dim3(6, 18),  wb>>>(wqkv, p_wqkvt, 192, 576);
    wconv<<<dim3(6, 6),   wb>>>(wo,   p_wot,   192, 192);
    wconv<<<dim3(6, 24),  wb>>>(w1,   p_w1t,   192, 768);
    wconv<<<dim3(24, 6),  wb>>>(w2,   p_w2t,   768, 192);

    ln_kernel<true><<<NTOK / 8, 256>>>(x, g1, b1, p_xw);
    mma_gemm<0><<<dim3(9, NTOK / 128), 256>>>(p_xw, p_wqkvt, bqkv, p_qkv,
                                              192, 576, nullptr);
    attn_kernel<<<1024, 256>>>(p_qkv, bt, p_attn);
    mma_gemm<2><<<dim3(3, NTOK / 128), 256>>>(p_attn, p_wot, bo, p_xo,
                                              192, 192, x);
    ln_kernel<false><<<NTOK / 8, 256>>>(p_xo, g2, b2, p_xn2);
    mma_gemm<1><<<dim3(12, NTOK / 128), 256>>>(p_xn2, p_w1t, bm1, p_h1,
                                               192, 768, nullptr);
    mma_gemm<3><<<dim3(3, NTOK / 128), 256>>>(p_h1, p_w2t, bm2, out,
                                              768, 192, p_xo);
}

// round 7
// speedup vs baseline: 3.5808x; 1.0228x over previous
#include <cuda_runtime.h>
#include <cuda_bf16.h>
#include <math.h>
#include <stdint.h>

#define NTOK 65536

// ---------------- scratch ----------------
__device__ __nv_bfloat16 g_xw  [(size_t)NTOK * 192];
__device__ __nv_bfloat16 g_qkv [(size_t)NTOK * 576];
__device__ __nv_bfloat16 g_attn[(size_t)NTOK * 192];
__device__ float         g_xo  [(size_t)NTOK * 192];
__device__ __nv_bfloat16 g_xn2 [(size_t)NTOK * 192];
__device__ __nv_bfloat16 g_h1  [(size_t)NTOK * 768];
__device__ __nv_bfloat16 g_wqkvt[576 * 192];
__device__ __nv_bfloat16 g_wot  [192 * 192];
__device__ __nv_bfloat16 g_w1t  [768 * 192];
__device__ __nv_bfloat16 g_w2t  [192 * 768];

// ---------------- helpers ----------------
__device__ __forceinline__ uint32_t smem_u32(const void* p) {
    uint32_t a;
    asm("{ .reg .u64 t; cvta.to.shared.u64 t, %1; cvt.u32.u64 %0, t; }" : "=r"(a) : "l"(p));
    return a;
}
__device__ __forceinline__ void ldsm_x4(uint32_t* r, uint32_t addr) {
    asm volatile("ldmatrix.sync.aligned.m8n8.x4.shared.b16 {%0,%1,%2,%3}, [%4];"
                 : "=r"(r[0]), "=r"(r[1]), "=r"(r[2]), "=r"(r[3]) : "r"(addr));
}
__device__ __forceinline__ void ldsm_x4t(uint32_t* r, uint32_t addr) {
    asm volatile("ldmatrix.sync.aligned.m8n8.x4.trans.shared.b16 {%0,%1,%2,%3}, [%4];"
                 : "=r"(r[0]), "=r"(r[1]), "=r"(r[2]), "=r"(r[3]) : "r"(addr));
}
__device__ __forceinline__ void mma_bf16(float* c, const uint32_t* a,
                                         uint32_t b0, uint32_t b1) {
    asm volatile(
        "mma.sync.aligned.m16n8k16.row.col.f32.bf16.bf16.f32 "
        "{%0,%1,%2,%3}, {%4,%5,%6,%7}, {%8,%9}, {%0,%1,%2,%3};"
        : "+f"(c[0]), "+f"(c[1]), "+f"(c[2]), "+f"(c[3])
        : "r"(a[0]), "r"(a[1]), "r"(a[2]), "r"(a[3]), "r"(b0), "r"(b1));
}
__device__ __forceinline__ uint32_t pack_bf16(float x, float y) {
    uint32_t r;
    asm("cvt.rn.bf16x2.f32 %0, %1, %2;" : "=r"(r) : "f"(y), "f"(x));
    return r;
}
__device__ __forceinline__ void cpa16(uint32_t dst, const void* src) {
    asm volatile("cp.async.cg.shared.global [%0], [%1], 16;" :: "r"(dst), "l"(src));
}

// ---------------- fused weight convert+transpose (4 weights, 1 launch) --------
__global__ void wconv4(const float* __restrict__ wa, __nv_bfloat16* __restrict__ oa,
                       const float* __restrict__ wb, __nv_bfloat16* __restrict__ ob,
                       const float* __restrict__ wc, __nv_bfloat16* __restrict__ oc,
                       const float* __restrict__ wd, __nv_bfloat16* __restrict__ od)
{
    __shared__ float t[32][33];
    const int bid = blockIdx.x;
    const float* in; __nv_bfloat16* out; int K, N, tile;
    if (bid < 108)      { in = wa; out = oa; K = 192; N = 576; tile = bid; }
    else if (bid < 144) { in = wb; out = ob; K = 192; N = 192; tile = bid - 108; }
    else if (bid < 288) { in = wc; out = oc; K = 192; N = 768; tile = bid - 144; }
    else                { in = wd; out = od; K = 768; N = 192; tile = bid - 288; }
    const int kt = tile % (K >> 5), nt = tile / (K >> 5);
    const int k0 = kt << 5, n0 = nt << 5;
    const int tx = threadIdx.x, ty = threadIdx.y;
#pragma unroll
    for (int i = 0; i < 32; i += 8)
        t[ty + i][tx] = in[(size_t)(k0 + ty + i) * N + n0 + tx];
    __syncthreads();
#pragma unroll
    for (int i = 0; i < 32; i += 8)
        out[(size_t)(n0 + ty + i) * K + k0 + tx] = __float2bfloat16(t[tx][ty + i]);
}

// ---------------- LayerNorm1 + shift + window partition ------------------------
__global__ __launch_bounds__(256)
void ln_kernel(const float* __restrict__ x, const float* __restrict__ g,
               const float* __restrict__ b, __nv_bfloat16* __restrict__ out)
{
    const int t = blockIdx.x * 8 + (threadIdx.x >> 5);
    const int lane = threadIdx.x & 31;
    const int b_ = t >> 6, n = t & 63;
    const int bb = b_ >> 9, widx = b_ & 511;
    const int hs = ((widx >> 6) << 2) + (n >> 4);
    const int ws = (((widx >> 3) & 7) << 2) + ((n >> 2) & 3);
    const int ds = ((widx & 7) << 2) + (n & 3);
    const size_t src = ((((size_t)bb * 32 + ((hs + 2) & 31)) * 32 + ((ws + 2) & 31)) * 32
                       + ((ds + 2) & 31));
    const float* xp = x + src * 192;
    float v[6];
    float s = 0.f;
#pragma unroll
    for (int r = 0; r < 6; ++r) { v[r] = xp[lane + 32 * r]; s += v[r]; }
#pragma unroll
    for (int o = 16; o > 0; o >>= 1) s += __shfl_xor_sync(0xffffffffu, s, o);
    const float mean = s * (1.f / 192.f);
    float vv = 0.f;
#pragma unroll
    for (int r = 0; r < 6; ++r) { const float d = v[r] - mean; vv += d * d; }
#pragma unroll
    for (int o = 16; o > 0; o >>= 1) vv += __shfl_xor_sync(0xffffffffu, vv, o);
    const float rstd = rsqrtf(vv * (1.f / 192.f) + 1e-5f);
    __nv_bfloat16* op = out + (size_t)t * 192;
#pragma unroll
    for (int r = 0; r < 6; ++r) {
        const int c = lane + 32 * r;
        op[c] = __float2bfloat16((v[r] - mean) * rstd * g[c] + b[c]);
    }
}

// ---------------- bf16 GEMM: BM=64, BN=192, BK=32, 3-stage cp.async ------------
// EPI 0: bias -> bf16 (ldc cols). EPI 1: bias + gelu -> bf16.
// EPI 2: bias + winrev-scatter + residual(x) -> xo fp32, then fused LN2 -> xn2 bf16.
// EPI 3: bias + residual(rows direct) -> fp32.
#define GSM_A 5120
#define GSM_B 15360
#define GSM_ST (GSM_A + GSM_B)
#define GSM_TOT (3 * GSM_ST)

template <int EPI>
__global__ __launch_bounds__(256)
void mma_gemm(const __nv_bfloat16* __restrict__ A, const __nv_bfloat16* __restrict__ Bt,
              const float* __restrict__ bias, void* __restrict__ Cv,
              int K, int ldc, const float* __restrict__ resid,
              const float* __restrict__ lg, const float* __restrict__ lb,
              __nv_bfloat16* __restrict__ xn2)
{
    constexpr bool OBF = (EPI == 0 || EPI == 1);
    extern __shared__ __align__(16) uint8_t dsm[];
    __shared__ float2 red[64][4];

    const int tid = threadIdx.x;
    const int warp = tid >> 5, lane = tid & 31;
    const int m0 = blockIdx.y << 6;
    const int n0 = blockIdx.x * 192;
    const int mwarp = (warp & 1) << 5;
    const int nwarp = (warp >> 1) * 48;
    const uint32_t sb = smem_u32(dsm);
    const int lrow = lane & 15, lkh = lane >> 4;
    const int NC = K >> 5;
    const int arow = tid >> 2, aseg = tid & 3;

    auto issue = [&](int c) {
        if (c < NC) {
            const int st = c % 3;
            const int kc = c << 5;
            const uint32_t ab = sb + st * GSM_ST;
            const uint32_t bb = ab + GSM_A;
            cpa16(ab + arow * 80 + aseg * 16,
                  A + (size_t)(m0 + arow) * K + kc + aseg * 8);
#pragma unroll
            for (int i = 0; i < 3; ++i) {
                const int idx = i * 256 + tid;
                const int row = idx >> 2, seg = idx & 3;
                cpa16(bb + row * 80 + seg * 16,
                      Bt + (size_t)(n0 + row) * K + kc + seg * 8);
            }
        }
        asm volatile("cp.async.commit_group;" ::: "memory");
    };

    float acc[2][6][4];
#pragma unroll
    for (int i = 0; i < 2; ++i)
#pragma unroll
        for (int j = 0; j < 6; ++j)
#pragma unroll
            for (int e = 0; e < 4; ++e) acc[i][j][e] = 0.f;

    issue(0);
    issue(1);
    for (int c = 0; c < NC; ++c) {
        asm volatile("cp.async.wait_group 1;" ::: "memory");
        __syncthreads();
        issue(c + 2);
        const int st = c % 3;
        const uint32_t ab = sb + st * GSM_ST;
        const uint32_t bb = ab + GSM_A;
#pragma unroll
        for (int kk = 0; kk < 2; ++kk) {
            uint32_t a[2][4], b[3][4];
#pragma unroll
            for (int mi = 0; mi < 2; ++mi)
                ldsm_x4(a[mi], ab + (mwarp + mi * 16 + lrow) * 80 + kk * 32 + lkh * 16);
#pragma unroll
            for (int ng = 0; ng < 3; ++ng)
                ldsm_x4(b[ng], bb + (nwarp + ng * 16 + lrow) * 80 + kk * 32 + lkh * 16);
#pragma unroll
            for (int mi = 0; mi < 2; ++mi)
#pragma unroll
                for (int nj = 0; nj < 6; ++nj)
                    mma_bf16(acc[mi][nj], a[mi],
                             b[nj >> 1][nj & 1], b[nj >> 1][(nj & 1) + 2]);
        }
    }

    // ---------------- epilogue ----------------
    const int g = lane >> 2, t2 = (lane & 3) * 2;

    if (EPI == 2) {
        // bias + residual + scatter-write xo; accumulate LN stats
        size_t tds[2][2];
#pragma unroll
        for (int mi = 0; mi < 2; ++mi) {
#pragma unroll
            for (int half = 0; half < 2; ++half) {
                const int r = mwarp + mi * 16 + g + half * 8;
                const int m = m0 + r;
                const int b_ = m >> 6, n = m & 63;
                const int bb2 = b_ >> 9, widx = b_ & 511;
                const int hs = ((widx >> 6) << 2) + (n >> 4);
                const int ws = (((widx >> 3) & 7) << 2) + ((n >> 2) & 3);
                const int ds = ((widx & 7) << 2) + (n & 3);
                const size_t td = ((((size_t)bb2 * 32 + ((hs + 2) & 31)) * 32
                                   + ((ws + 2) & 31)) * 32 + ((ds + 2) & 31));
                tds[mi][half] = td;
                float s = 0.f, sq = 0.f;
#pragma unroll
                for (int nj = 0; nj < 6; ++nj) {
                    const int col = nwarp + nj * 8 + t2;
                    const float2 bv = *(const float2*)(bias + col);
                    const float2 rv = *(const float2*)(resid + td * 192 + col);
                    float ox = acc[mi][nj][half * 2 + 0] + bv.x + rv.x;
                    float oy = acc[mi][nj][half * 2 + 1] + bv.y + rv.y;
                    acc[mi][nj][half * 2 + 0] = ox;
                    acc[mi][nj][half * 2 + 1] = oy;
                    *(float2*)((float*)Cv + td * 192 + col) = make_float2(ox, oy);
                    s += ox + oy;
                    sq += ox * ox + oy * oy;
                }
                s  += __shfl_xor_sync(0xffffffffu, s, 1);
                s  += __shfl_xor_sync(0xffffffffu, s, 2);
                sq += __shfl_xor_sync(0xffffffffu, sq, 1);
                sq += __shfl_xor_sync(0xffffffffu, sq, 2);
                if ((lane & 3) == 0) red[r][warp >> 1] = make_float2(s, sq);
            }
        }
        __syncthreads();
#pragma unroll
        for (int mi = 0; mi < 2; ++mi) {
#pragma unroll
            for (int half = 0; half < 2; ++half) {
                const int r = mwarp + mi * 16 + g + half * 8;
                const float2 r0 = red[r][0], r1 = red[r][1];
                const float2 r2 = red[r][2], r3 = red[r][3];
                const float s = r0.x + r1.x + r2.x + r3.x;
                const float sq = r0.y + r1.y + r2.y + r3.y;
                const float mean = s * (1.f / 192.f);
                const float var = sq * (1.f / 192.f) - mean * mean;
                const float rstd = rsqrtf(var + 1e-5f);
                const size_t td = tds[mi][half];
#pragma unroll
                for (int nj = 0; nj < 6; ++nj) {
                    const int col = nwarp + nj * 8 + t2;
                    const float2 gv = *(const float2*)(lg + col);
                    const float2 bv2 = *(const float2*)(lb + col);
                    const float vx = (acc[mi][nj][half * 2 + 0] - mean) * rstd * gv.x + bv2.x;
                    const float vy = (acc[mi][nj][half * 2 + 1] - mean) * rstd * gv.y + bv2.y;
                    *(uint32_t*)(xn2 + td * 192 + col) = pack_bf16(vx, vy);
                }
            }
        }
        return;
    }

#pragma unroll
    for (int mi = 0; mi < 2; ++mi) {
#pragma unroll
        for (int half = 0; half < 2; ++half) {
            const int m = m0 + mwarp + mi * 16 + g + half * 8;
#pragma unroll
            for (int nj = 0; nj < 6; ++nj) {
                const int col = n0 + nwarp + nj * 8 + t2;
                const float2 bv = *(const float2*)(bias + col);
                float ox = acc[mi][nj][half * 2 + 0] + bv.x;
                float oy = acc[mi][nj][half * 2 + 1] + bv.y;
                if (EPI == 1) {
                    const float kk = 0.70710678118654752f;
                    ox = 0.5f * ox * (1.f + erff(ox * kk));
                    oy = 0.5f * oy * (1.f + erff(oy * kk));
                }
                if (EPI == 3) {
                    const float2 rv = *(const float2*)(resid + (size_t)m * 192 + col);
                    ox += rv.x; oy += rv.y;
                }
                if (OBF) {
                    *(uint32_t*)((__nv_bfloat16*)Cv + (size_t)m * ldc + col) = pack_bf16(ox, oy);
                } else {
                    *(float2*)((float*)Cv + (size_t)m * ldc + col) = make_float2(ox, oy);
                }
            }
        }
    }
}

// ---------------- windowed attention (tensor-core bf16, 2 heads/CTA) ----------
__global__ __launch_bounds__(256)
void attn_kernel(const __nv_bfloat16* __restrict__ qkv, const float* __restrict__ bt,
                 __nv_bfloat16* __restrict__ out)
{
    __shared__ __align__(16) uint8_t qs[64 * 80];
    __shared__ __align__(16) uint8_t ks[64 * 80];
    __shared__ __align__(16) uint8_t vs[64 * 80];
    __shared__ __align__(16) uint8_t ps[64 * 144];
    __shared__ float ss[64 * 65];
    __shared__ int   grp[64];

    const int tid = threadIdx.x;
    const int wnd = blockIdx.x & 1023;
    const int hb = (blockIdx.x >> 10) << 1;
    const int widx = wnd & 511;
    const int wh = widx >> 6, ww = (widx >> 3) & 7, wd = widx & 7;

    if (tid < 64) {
        const int i = tid >> 4, j = (tid >> 2) & 3, k2 = tid & 3;
        const int rh = (wh < 7) ? 0 : ((i < 2) ? 1 : 2);
        const int rw = (ww < 7) ? 0 : ((j < 2) ? 1 : 2);
        const int rd = (wd < 7) ? 0 : ((k2 < 2) ? 1 : 2);
        grp[tid] = rh * 9 + rw * 3 + rd;
    }

    const int warp = tid >> 5, lane = tid & 31;
    const int lrow = lane & 15, lkh = lane >> 4;
    const int g = lane >> 2, t2 = (lane & 3) * 2;
    const int row = tid >> 2, seg = tid & 3;
    const int sr = tid >> 2, sg = tid & 3;
    const uint32_t qs_b = smem_u32(qs), ks_b = smem_u32(ks);
    const uint32_t vs_b = smem_u32(vs), ps_b = smem_u32(ps);
    const size_t base = ((size_t)wnd * 64 + row) * 576 + seg * 8;
    const float scl = 0.17677669529663687f;

    const int msl = (warp & 3) * 16;
    const int nh  = (warp >> 2) * 32;
    const int dh  = (warp >> 2) * 16;

    for (int h = hb; h < hb + 2; ++h) {
        const __nv_bfloat16* qp = qkv + base + h * 32;
        *(uint4*)(qs + row * 80 + seg * 16) = *(const uint4*)(qp);
        *(uint4*)(ks + row * 80 + seg * 16) = *(const uint4*)(qp + 192);
        *(uint4*)(vs + row * 80 + seg * 16) = *(const uint4*)(qp + 384);
        __syncthreads();

        float acc[4][4];
#pragma unroll
        for (int nj = 0; nj < 4; ++nj)
#pragma unroll
            for (int e = 0; e < 4; ++e) acc[nj][e] = 0.f;
#pragma unroll
        for (int kk = 0; kk < 2; ++kk) {
            uint32_t a[4], b[2][4];
            ldsm_x4(a, qs_b + (msl + lrow) * 80 + kk * 32 + lkh * 16);
#pragma unroll
            for (int ng = 0; ng < 2; ++ng)
                ldsm_x4(b[ng], ks_b + (nh + ng * 16 + lrow) * 80 + kk * 32 + lkh * 16);
#pragma unroll
            for (int nj = 0; nj < 4; ++nj)
                mma_bf16(acc[nj], a, b[nj >> 1][nj & 1], b[nj >> 1][(nj & 1) + 2]);
        }
#pragma unroll
        for (int nj = 0; nj < 4; ++nj)
#pragma unroll
            for (int e = 0; e < 4; ++e) {
                const int i = msl + g + (e >> 1) * 8;
                const int j = nh + nj * 8 + t2 + (e & 1);
                const int idx = ((i >> 4) - (j >> 4) + 3) * 49
                              + (((i >> 2) & 3) - ((j >> 2) & 3) + 3) * 7
                              + ((i & 3) - (j & 3) + 3);
                const float bias = __ldg(&bt[idx * 6 + h]);
                const float mv = (grp[i] == grp[j]) ? 0.f : -100.f;
                ss[i * 65 + j] = acc[nj][e] * scl + bias + mv;
            }
        __syncthreads();

        float* rowp = &ss[sr * 65 + sg * 16];
        float mx = rowp[0];
#pragma unroll
        for (int c = 1; c < 16; ++c) mx = fmaxf(mx, rowp[c]);
        mx = fmaxf(mx, __shfl_xor_sync(0xffffffffu, mx, 1));
        mx = fmaxf(mx, __shfl_xor_sync(0xffffffffu, mx, 2));
        float sum = 0.f;
        float ev[16];
#pragma unroll
        for (int c = 0; c < 16; ++c) { ev[c] = __expf(rowp[c] - mx); sum += ev[c]; }
        sum += __shfl_xor_sync(0xffffffffu, sum, 1);
        sum += __shfl_xor_sync(0xffffffffu, sum, 2);
        const float rinv = 1.f / sum;
        uint32_t pk[8];
#pragma unroll
        for (int c = 0; c < 8; ++c)
            pk[c] = pack_bf16(ev[2 * c] * rinv, ev[2 * c + 1] * rinv);
        *(uint4*)(ps + sr * 144 + sg * 32)      = make_uint4(pk[0], pk[1], pk[2], pk[3]);
        *(uint4*)(ps + sr * 144 + sg * 32 + 16) = make_uint4(pk[4], pk[5], pk[6], pk[7]);
        __syncthreads();

        float o[2][4];
#pragma unroll
        for (int nt = 0; nt < 2; ++nt)
#pragma unroll
            for (int e = 0; e < 4; ++e) o[nt][e] = 0.f;
#pragma unroll
        for (int kc = 0; kc < 4; ++kc) {
            uint32_t a[4], b[4];
            ldsm_x4(a, ps_b + (msl + lrow) * 144 + kc * 32 + lkh * 16);
            ldsm_x4t(b, vs_b + (kc * 16 + lrow) * 80 + (dh + lkh * 8) * 2);
            mma_bf16(o[0], a, b[0], b[1]);
            mma_bf16(o[1], a, b[2], b[3]);
        }
#pragma unroll
        for (int nt = 0; nt < 2; ++nt) {
            const int d = dh + nt * 8 + t2;
            __nv_bfloat16* op0 = out + ((size_t)wnd * 64 + msl + g) * 192 + h * 32 + d;
            __nv_bfloat16* op1 = op0 + 8 * 192;
            *(uint32_t*)op0 = pack_bf16(o[nt][0], o[nt][1]);
            *(uint32_t*)op1 = pack_bf16(o[nt][2], o[nt][3]);
        }
        __syncthreads();
    }
}

// ---------------- launch --------------------------------------------------------
extern "C" void kernel_launch(void* const* d_in, const int* in_sizes, int n_in,
                              void* d_out, int out_size)
{
    const float* x    = (const float*)d_in[0];
    const float* g1   = (const float*)d_in[1];
    const float* b1   = (const float*)d_in[2];
    const float* wqkv = (const float*)d_in[3];
    const float* bqkv = (const float*)d_in[4];
    const float* wo   = (const float*)d_in[5];
    const float* bo   = (const float*)d_in[6];
    const float* bt   = (const float*)d_in[7];
    const float* g2   = (const float*)d_in[8];
    const float* b2   = (const float*)d_in[9];
    const float* w1   = (const float*)d_in[10];
    const float* bm1  = (const float*)d_in[11];
    const float* w2   = (const float*)d_in[12];
    const float* bm2  = (const float*)d_in[13];
    float* out = (float*)d_out;

    __nv_bfloat16 *p_xw, *p_qkv, *p_attn, *p_xn2, *p_h1;
    __nv_bfloat16 *p_wqkvt, *p_wot, *p_w1t, *p_w2t;
    float *p_xo;
    cudaGetSymbolAddress((void**)&p_xw,    g_xw);
    cudaGetSymbolAddress((void**)&p_qkv,   g_qkv);
    cudaGetSymbolAddress((void**)&p_attn,  g_attn);
    cudaGetSymbolAddress((void**)&p_xo,    g_xo);
    cudaGetSymbolAddress((void**)&p_xn2,   g_xn2);
    cudaGetSymbolAddress((void**)&p_h1,    g_h1);
    cudaGetSymbolAddress((void**)&p_wqkvt, g_wqkvt);
    cudaGetSymbolAddress((void**)&p_wot,   g_wot);
    cudaGetSymbolAddress((void**)&p_w1t,   g_w1t);
    cudaGetSymbolAddress((void**)&p_w2t,   g_w2t);

    cudaFuncSetAttribute(mma_gemm<0>, cudaFuncAttributeMaxDynamicSharedMemorySize, GSM_TOT);
    cudaFuncSetAttribute(mma_gemm<1>, cudaFuncAttributeMaxDynamicSharedMemorySize, GSM_TOT);
    cudaFuncSetAttribute(mma_gemm<2>, cudaFuncAttributeMaxDynamicSharedMemorySize, GSM_TOT);
    cudaFuncSetAttribute(mma_gemm<3>, cudaFuncAttributeMaxDynamicSharedMemorySize, GSM_TOT);

    // 0) all weight transposes in one launch
    wconv4<<<432, dim3(32, 8)>>>(wqkv, p_wqkvt, wo, p_wot, w1, p_w1t, w2, p_w2t);
    // 1) LN1 + shift + window partition
    ln_kernel<<<NTOK / 8, 256>>>(x, g1, b1, p_xw);
    // 2) qkv
    mma_gemm<0><<<dim3(3, NTOK / 64), 256, GSM_TOT>>>(p_xw, p_wqkvt, bqkv, p_qkv,
                                                      192, 576, nullptr, nullptr, nullptr, nullptr);
    // 3) attention (2 heads per CTA)
    attn_kernel<<<3072, 256>>>(p_qkv, bt, p_attn);
    // 4) proj + winrev + residual -> xo, fused LN2 -> xn2
    mma_gemm<2><<<dim3(1, NTOK / 64), 256, GSM_TOT>>>(p_attn, p_wot, bo, p_xo,
                                                      192, 192, x, g2, b2, p_xn2);
    // 5) mlp1 = gelu(xn2 @ w1 + bm1)
    mma_gemm<1><<<dim3(4, NTOK / 64), 256, GSM_TOT>>>(p_xn2, p_w1t, bm1, p_h1,
                                                      192, 768, nullptr, nullptr, nullptr, nullptr);
    // 6) out = xo + h1 @ w2 + bm2
    mma_gemm<3><<<dim3(1, NTOK / 64), 256, GSM_TOT>>>(p_h1, p_w2t, bm2, out,
                                                      768, 192, p_xo, nullptr, nullptr, nullptr);
}

// round 8
// speedup vs baseline: 3.8180x; 1.0662x over previous
#include <cuda_runtime.h>
#include <cuda_bf16.h>
#include <math.h>
#include <stdint.h>

#define NTOK 65536

// ---------------- scratch ----------------
__device__ __nv_bfloat16 g_xw  [(size_t)NTOK * 192];
__device__ __nv_bfloat16 g_qkv [(size_t)NTOK * 576];
__device__ __nv_bfloat16 g_attn[(size_t)NTOK * 192];
__device__ float         g_xo  [(size_t)NTOK * 192];
__device__ __nv_bfloat16 g_xn2 [(size_t)NTOK * 192];
__device__ __nv_bfloat16 g_h1  [(size_t)NTOK * 768];
__device__ __nv_bfloat16 g_wqkvt[576 * 192];
__device__ __nv_bfloat16 g_wot  [192 * 192];
__device__ __nv_bfloat16 g_w1t  [768 * 192];
__device__ __nv_bfloat16 g_w2t  [192 * 768];

// ---------------- helpers ----------------
__device__ __forceinline__ uint32_t smem_u32(const void* p) {
    uint32_t a;
    asm("{ .reg .u64 t; cvta.to.shared.u64 t, %1; cvt.u32.u64 %0, t; }" : "=r"(a) : "l"(p));
    return a;
}
__device__ __forceinline__ void ldsm_x4(uint32_t* r, uint32_t addr) {
    asm volatile("ldmatrix.sync.aligned.m8n8.x4.shared.b16 {%0,%1,%2,%3}, [%4];"
                 : "=r"(r[0]), "=r"(r[1]), "=r"(r[2]), "=r"(r[3]) : "r"(addr));
}
__device__ __forceinline__ void ldsm_x4t(uint32_t* r, uint32_t addr) {
    asm volatile("ldmatrix.sync.aligned.m8n8.x4.trans.shared.b16 {%0,%1,%2,%3}, [%4];"
                 : "=r"(r[0]), "=r"(r[1]), "=r"(r[2]), "=r"(r[3]) : "r"(addr));
}
__device__ __forceinline__ void mma_bf16(float* c, const uint32_t* a,
                                         uint32_t b0, uint32_t b1) {
    asm volatile(
        "mma.sync.aligned.m16n8k16.row.col.f32.bf16.bf16.f32 "
        "{%0,%1,%2,%3}, {%4,%5,%6,%7}, {%8,%9}, {%0,%1,%2,%3};"
        : "+f"(c[0]), "+f"(c[1]), "+f"(c[2]), "+f"(c[3])
        : "r"(a[0]), "r"(a[1]), "r"(a[2]), "r"(a[3]), "r"(b0), "r"(b1));
}
__device__ __forceinline__ uint32_t pack_bf16(float x, float y) {
    uint32_t r;
    asm("cvt.rn.bf16x2.f32 %0, %1, %2;" : "=r"(r) : "f"(y), "f"(x));
    return r;
}
__device__ __forceinline__ void cpa16(uint32_t dst, const void* src) {
    asm volatile("cp.async.cg.shared.global [%0], [%1], 16;" :: "r"(dst), "l"(src));
}

// ---------------- fused weight convert+transpose ------------------------------
__global__ void wconv4(const float* __restrict__ wa, __nv_bfloat16* __restrict__ oa,
                       const float* __restrict__ wb, __nv_bfloat16* __restrict__ ob,
                       const float* __restrict__ wc, __nv_bfloat16* __restrict__ oc,
                       const float* __restrict__ wd, __nv_bfloat16* __restrict__ od)
{
    __shared__ float t[32][33];
    const int bid = blockIdx.x;
    const float* in; __nv_bfloat16* out; int K, N, tile;
    if (bid < 108)      { in = wa; out = oa; K = 192; N = 576; tile = bid; }
    else if (bid < 144) { in = wb; out = ob; K = 192; N = 192; tile = bid - 108; }
    else if (bid < 288) { in = wc; out = oc; K = 192; N = 768; tile = bid - 144; }
    else                { in = wd; out = od; K = 768; N = 192; tile = bid - 288; }
    const int kt = tile % (K >> 5), nt = tile / (K >> 5);
    const int k0 = kt << 5, n0 = nt << 5;
    const int tx = threadIdx.x, ty = threadIdx.y;
#pragma unroll
    for (int i = 0; i < 32; i += 8)
        t[ty + i][tx] = in[(size_t)(k0 + ty + i) * N + n0 + tx];
    __syncthreads();
#pragma unroll
    for (int i = 0; i < 32; i += 8)
        out[(size_t)(n0 + ty + i) * K + k0 + tx] = __float2bfloat16(t[tx][ty + i]);
}

// ---------------- LayerNorm1 + shift + window partition ------------------------
__global__ __launch_bounds__(256)
void ln_kernel(const float* __restrict__ x, const float* __restrict__ g,
               const float* __restrict__ b, __nv_bfloat16* __restrict__ out)
{
    const int t = blockIdx.x * 8 + (threadIdx.x >> 5);
    const int lane = threadIdx.x & 31;
    const int b_ = t >> 6, n = t & 63;
    const int bb = b_ >> 9, widx = b_ & 511;
    const int hs = ((widx >> 6) << 2) + (n >> 4);
    const int ws = (((widx >> 3) & 7) << 2) + ((n >> 2) & 3);
    const int ds = ((widx & 7) << 2) + (n & 3);
    const size_t src = ((((size_t)bb * 32 + ((hs + 2) & 31)) * 32 + ((ws + 2) & 31)) * 32
                       + ((ds + 2) & 31));
    const float* xp = x + src * 192;
    float v[6];
    float s = 0.f;
#pragma unroll
    for (int r = 0; r < 6; ++r) { v[r] = xp[lane + 32 * r]; s += v[r]; }
#pragma unroll
    for (int o = 16; o > 0; o >>= 1) s += __shfl_xor_sync(0xffffffffu, s, o);
    const float mean = s * (1.f / 192.f);
    float vv = 0.f;
#pragma unroll
    for (int r = 0; r < 6; ++r) { const float d = v[r] - mean; vv += d * d; }
#pragma unroll
    for (int o = 16; o > 0; o >>= 1) vv += __shfl_xor_sync(0xffffffffu, vv, o);
    const float rstd = rsqrtf(vv * (1.f / 192.f) + 1e-5f);
    __nv_bfloat16* op = out + (size_t)t * 192;
#pragma unroll
    for (int r = 0; r < 6; ++r) {
        const int c = lane + 32 * r;
        op[c] = __float2bfloat16((v[r] - mean) * rstd * g[c] + b[c]);
    }
}

// ---------------- bf16 GEMM: BM=64, BN=192, BK=32, 3-stage cp.async ------------
#define GSM_A 5120
#define GSM_B 15360
#define GSM_ST (GSM_A + GSM_B)
#define GSM_TOT (3 * GSM_ST)

template <int EPI>
__global__ __launch_bounds__(256)
void mma_gemm(const __nv_bfloat16* __restrict__ A, const __nv_bfloat16* __restrict__ Bt,
              const float* __restrict__ bias, void* __restrict__ Cv,
              int K, int ldc, const float* __restrict__ resid,
              const float* __restrict__ lg, const float* __restrict__ lb,
              __nv_bfloat16* __restrict__ xn2)
{
    constexpr bool OBF = (EPI == 0 || EPI == 1);
    extern __shared__ __align__(16) uint8_t dsm[];
    __shared__ float2 red[64][4];

    const int tid = threadIdx.x;
    const int warp = tid >> 5, lane = tid & 31;
    const int m0 = blockIdx.y << 6;
    const int n0 = blockIdx.x * 192;
    const int mwarp = (warp & 1) << 5;
    const int nwarp = (warp >> 1) * 48;
    const uint32_t sb = smem_u32(dsm);
    const int lrow = lane & 15, lkh = lane >> 4;
    const int NC = K >> 5;
    const int arow = tid >> 2, aseg = tid & 3;

    auto issue = [&](int c) {
        if (c < NC) {
            const int st = c % 3;
            const int kc = c << 5;
            const uint32_t ab = sb + st * GSM_ST;
            const uint32_t bb = ab + GSM_A;
            cpa16(ab + arow * 80 + aseg * 16,
                  A + (size_t)(m0 + arow) * K + kc + aseg * 8);
#pragma unroll
            for (int i = 0; i < 3; ++i) {
                const int idx = i * 256 + tid;
                const int row = idx >> 2, seg = idx & 3;
                cpa16(bb + row * 80 + seg * 16,
                      Bt + (size_t)(n0 + row) * K + kc + seg * 8);
            }
        }
        asm volatile("cp.async.commit_group;" ::: "memory");
    };

    float acc[2][6][4];
#pragma unroll
    for (int i = 0; i < 2; ++i)
#pragma unroll
        for (int j = 0; j < 6; ++j)
#pragma unroll
            for (int e = 0; e < 4; ++e) acc[i][j][e] = 0.f;

    issue(0);
    issue(1);
    for (int c = 0; c < NC; ++c) {
        asm volatile("cp.async.wait_group 1;" ::: "memory");
        __syncthreads();
        issue(c + 2);
        const int st = c % 3;
        const uint32_t ab = sb + st * GSM_ST;
        const uint32_t bb = ab + GSM_A;
#pragma unroll
        for (int kk = 0; kk < 2; ++kk) {
            uint32_t a[2][4], b[3][4];
#pragma unroll
            for (int mi = 0; mi < 2; ++mi)
                ldsm_x4(a[mi], ab + (mwarp + mi * 16 + lrow) * 80 + kk * 32 + lkh * 16);
#pragma unroll
            for (int ng = 0; ng < 3; ++ng)
                ldsm_x4(b[ng], bb + (nwarp + ng * 16 + lrow) * 80 + kk * 32 + lkh * 16);
#pragma unroll
            for (int mi = 0; mi < 2; ++mi)
#pragma unroll
                for (int nj = 0; nj < 6; ++nj)
                    mma_bf16(acc[mi][nj], a[mi],
                             b[nj >> 1][nj & 1], b[nj >> 1][(nj & 1) + 2]);
        }
    }

    const int g = lane >> 2, t2 = (lane & 3) * 2;

    if (EPI == 2) {
        size_t tds[2][2];
#pragma unroll
        for (int mi = 0; mi < 2; ++mi) {
#pragma unroll
            for (int half = 0; half < 2; ++half) {
                const int r = mwarp + mi * 16 + g + half * 8;
                const int m = m0 + r;
                const int b_ = m >> 6, n = m & 63;
                const int bb2 = b_ >> 9, widx = b_ & 511;
                const int hs = ((widx >> 6) << 2) + (n >> 4);
                const int ws = (((widx >> 3) & 7) << 2) + ((n >> 2) & 3);
                const int ds = ((widx & 7) << 2) + (n & 3);
                const size_t td = ((((size_t)bb2 * 32 + ((hs + 2) & 31)) * 32
                                   + ((ws + 2) & 31)) * 32 + ((ds + 2) & 31));
                tds[mi][half] = td;
                float s = 0.f, sq = 0.f;
#pragma unroll
                for (int nj = 0; nj < 6; ++nj) {
                    const int col = nwarp + nj * 8 + t2;
                    const float2 bv = *(const float2*)(bias + col);
                    const float2 rv = *(const float2*)(resid + td * 192 + col);
                    float ox = acc[mi][nj][half * 2 + 0] + bv.x + rv.x;
                    float oy = acc[mi][nj][half * 2 + 1] + bv.y + rv.y;
                    acc[mi][nj][half * 2 + 0] = ox;
                    acc[mi][nj][half * 2 + 1] = oy;
                    *(float2*)((float*)Cv + td * 192 + col) = make_float2(ox, oy);
                    s += ox + oy;
                    sq += ox * ox + oy * oy;
                }
                s  += __shfl_xor_sync(0xffffffffu, s, 1);
                s  += __shfl_xor_sync(0xffffffffu, s, 2);
                sq += __shfl_xor_sync(0xffffffffu, sq, 1);
                sq += __shfl_xor_sync(0xffffffffu, sq, 2);
                if ((lane & 3) == 0) red[r][warp >> 1] = make_float2(s, sq);
            }
        }
        __syncthreads();
#pragma unroll
        for (int mi = 0; mi < 2; ++mi) {
#pragma unroll
            for (int half = 0; half < 2; ++half) {
                const int r = mwarp + mi * 16 + g + half * 8;
                const float2 r0 = red[r][0], r1 = red[r][1];
                const float2 r2 = red[r][2], r3 = red[r][3];
                const float s = r0.x + r1.x + r2.x + r3.x;
                const float sq = r0.y + r1.y + r2.y + r3.y;
                const float mean = s * (1.f / 192.f);
                const float var = sq * (1.f / 192.f) - mean * mean;
                const float rstd = rsqrtf(var + 1e-5f);
                const size_t td = tds[mi][half];
#pragma unroll
                for (int nj = 0; nj < 6; ++nj) {
                    const int col = nwarp + nj * 8 + t2;
                    const float2 gv = *(const float2*)(lg + col);
                    const float2 bv2 = *(const float2*)(lb + col);
                    const float vx = (acc[mi][nj][half * 2 + 0] - mean) * rstd * gv.x + bv2.x;
                    const float vy = (acc[mi][nj][half * 2 + 1] - mean) * rstd * gv.y + bv2.y;
                    *(uint32_t*)(xn2 + td * 192 + col) = pack_bf16(vx, vy);
                }
            }
        }
        return;
    }

#pragma unroll
    for (int mi = 0; mi < 2; ++mi) {
#pragma unroll
        for (int half = 0; half < 2; ++half) {
            const int m = m0 + mwarp + mi * 16 + g + half * 8;
#pragma unroll
            for (int nj = 0; nj < 6; ++nj) {
                const int col = n0 + nwarp + nj * 8 + t2;
                const float2 bv = *(const float2*)(bias + col);
                float ox = acc[mi][nj][half * 2 + 0] + bv.x;
                float oy = acc[mi][nj][half * 2 + 1] + bv.y;
                if (EPI == 1) {
                    const float kk = 0.70710678118654752f;
                    ox = 0.5f * ox * (1.f + erff(ox * kk));
                    oy = 0.5f * oy * (1.f + erff(oy * kk));
                }
                if (EPI == 3) {
                    const float2 rv = *(const float2*)(resid + (size_t)m * 192 + col);
                    ox += rv.x; oy += rv.y;
                }
                if (OBF) {
                    *(uint32_t*)((__nv_bfloat16*)Cv + (size_t)m * ldc + col) = pack_bf16(ox, oy);
                } else {
                    *(float2*)((float*)Cv + (size_t)m * ldc + col) = make_float2(ox, oy);
                }
            }
        }
    }
}

// ---------------- windowed attention: register-resident P, 1 sync --------------
// grid 3072: CTA = (window, head pair). warp = (head in pair, 16-row slab).
// Scores for full 64 key cols stay in registers; softmax via 4-lane shfl;
// P packs directly from C-frag into PV A-frag.
__global__ __launch_bounds__(256)
void attn_kernel(const __nv_bfloat16* __restrict__ qkv, const float* __restrict__ bt,
                 __nv_bfloat16* __restrict__ out)
{
    __shared__ __align__(16) uint8_t qs[64 * 144];
    __shared__ __align__(16) uint8_t ks[64 * 144];
    __shared__ __align__(16) uint8_t vs[64 * 144];
    __shared__ int grp[64];

    const int tid = threadIdx.x;
    const int wnd = blockIdx.x & 1023;
    const int hb = (blockIdx.x >> 10) << 1;
    const int widx = wnd & 511;
    const int wh = widx >> 6, ww = (widx >> 3) & 7, wd = widx & 7;

    if (tid < 64) {
        const int i = tid >> 4, j = (tid >> 2) & 3, k2 = tid & 3;
        const int rh = (wh < 7) ? 0 : ((i < 2) ? 1 : 2);
        const int rw = (ww < 7) ? 0 : ((j < 2) ? 1 : 2);
        const int rd = (wd < 7) ? 0 : ((k2 < 2) ? 1 : 2);
        grp[tid] = rh * 9 + rw * 3 + rd;
    }

    // ---- load q,k,v for both heads (64 tokens x 64 dims each) ----
    {
        const int r = tid >> 2, s4 = tid & 3;
        const __nv_bfloat16* tp = qkv + ((size_t)wnd * 64 + r) * 576 + hb * 32;
        *(uint4*)(qs + r * 144 + s4 * 16)       = *(const uint4*)(tp + s4 * 8);
        *(uint4*)(qs + r * 144 + s4 * 16 + 64)  = *(const uint4*)(tp + s4 * 8 + 32);
        *(uint4*)(ks + r * 144 + s4 * 16)       = *(const uint4*)(tp + 192 + s4 * 8);
        *(uint4*)(ks + r * 144 + s4 * 16 + 64)  = *(const uint4*)(tp + 192 + s4 * 8 + 32);
        *(uint4*)(vs + r * 144 + s4 * 16)       = *(const uint4*)(tp + 384 + s4 * 8);
        *(uint4*)(vs + r * 144 + s4 * 16 + 64)  = *(const uint4*)(tp + 384 + s4 * 8 + 32);
    }
    __syncthreads();

    const int warp = tid >> 5, lane = tid & 31;
    const int lrow = lane & 15, lkh = lane >> 4;
    const int g = lane >> 2, t2 = (lane & 3) * 2;
    const int h = hb + (warp >> 2);
    const int hoff = (warp >> 2) * 64;       // byte offset of this head's 32 dims
    const int msl = (warp & 3) * 16;         // query-row slab
    const uint32_t qs_b = smem_u32(qs), ks_b = smem_u32(ks), vs_b = smem_u32(vs);
    const float scl = 0.17677669529663687f;

    // ---- scores: 16 rows x 64 cols, all in registers ----
    float acc[8][4];
#pragma unroll
    for (int nj = 0; nj < 8; ++nj)
#pragma unroll
        for (int e = 0; e < 4; ++e) acc[nj][e] = 0.f;
#pragma unroll
    for (int kk = 0; kk < 2; ++kk) {
        uint32_t a[4];
        ldsm_x4(a, qs_b + (msl + lrow) * 144 + hoff + kk * 32 + lkh * 16);
#pragma unroll
        for (int ng = 0; ng < 4; ++ng) {
            uint32_t b[4];
            ldsm_x4(b, ks_b + (ng * 16 + lrow) * 144 + hoff + kk * 32 + lkh * 16);
            mma_bf16(acc[2 * ng],     a, b[0], b[2]);
            mma_bf16(acc[2 * ng + 1], a, b[1], b[3]);
        }
    }

    // ---- scale + bias + mask ----
    const int i0 = msl + g, i1 = i0 + 8;
    const int gi0 = grp[i0], gi1 = grp[i1];
#pragma unroll
    for (int nj = 0; nj < 8; ++nj)
#pragma unroll
        for (int e = 0; e < 4; ++e) {
            const int i = (e >> 1) ? i1 : i0;
            const int j = nj * 8 + t2 + (e & 1);
            const int idx = ((i >> 4) - (j >> 4) + 3) * 49
                          + (((i >> 2) & 3) - ((j >> 2) & 3) + 3) * 7
                          + ((i & 3) - (j & 3) + 3);
            const float bias = __ldg(&bt[idx * 6 + h]);
            const int gj = grp[j];
            const float mv = (((e >> 1) ? gi1 : gi0) == gj) ? 0.f : -100.f;
            acc[nj][e] = acc[nj][e] * scl + bias + mv;
        }

    // ---- softmax (rows i0 and i1) via 4-lane shfl ----
    float mx0 = -1e30f, mx1 = -1e30f;
#pragma unroll
    for (int nj = 0; nj < 8; ++nj) {
        mx0 = fmaxf(mx0, fmaxf(acc[nj][0], acc[nj][1]));
        mx1 = fmaxf(mx1, fmaxf(acc[nj][2], acc[nj][3]));
    }
    mx0 = fmaxf(mx0, __shfl_xor_sync(0xffffffffu, mx0, 1));
    mx0 = fmaxf(mx0, __shfl_xor_sync(0xffffffffu, mx0, 2));
    mx1 = fmaxf(mx1, __shfl_xor_sync(0xffffffffu, mx1, 1));
    mx1 = fmaxf(mx1, __shfl_xor_sync(0xffffffffu, mx1, 2));
    float s0 = 0.f, s1 = 0.f;
#pragma unroll
    for (int nj = 0; nj < 8; ++nj) {
        acc[nj][0] = __expf(acc[nj][0] - mx0); s0 += acc[nj][0];
        acc[nj][1] = __expf(acc[nj][1] - mx0); s0 += acc[nj][1];
        acc[nj][2] = __expf(acc[nj][2] - mx1); s1 += acc[nj][2];
        acc[nj][3] = __expf(acc[nj][3] - mx1); s1 += acc[nj][3];
    }
    s0 += __shfl_xor_sync(0xffffffffu, s0, 1);
    s0 += __shfl_xor_sync(0xffffffffu, s0, 2);
    s1 += __shfl_xor_sync(0xffffffffu, s1, 1);
    s1 += __shfl_xor_sync(0xffffffffu, s1, 2);
    const float r0 = 1.f / s0, r1 = 1.f / s1;

    // ---- P (C-frag) -> A-frag pack, PV mma ----
    uint32_t pa[4][4];
#pragma unroll
    for (int kc = 0; kc < 4; ++kc) {
        pa[kc][0] = pack_bf16(acc[2 * kc][0] * r0,     acc[2 * kc][1] * r0);
        pa[kc][1] = pack_bf16(acc[2 * kc][2] * r1,     acc[2 * kc][3] * r1);
        pa[kc][2] = pack_bf16(acc[2 * kc + 1][0] * r0, acc[2 * kc + 1][1] * r0);
        pa[kc][3] = pack_bf16(acc[2 * kc + 1][2] * r1, acc[2 * kc + 1][3] * r1);
    }
    float o[4][4];
#pragma unroll
    for (int dj = 0; dj < 4; ++dj)
#pragma unroll
        for (int e = 0; e < 4; ++e) o[dj][e] = 0.f;
#pragma unroll
    for (int kc = 0; kc < 4; ++kc) {
#pragma unroll
        for (int dt = 0; dt < 2; ++dt) {
            uint32_t b[4];
            ldsm_x4t(b, vs_b + (kc * 16 + lrow) * 144 + hoff + dt * 32 + lkh * 16);
            mma_bf16(o[2 * dt],     pa[kc], b[0], b[1]);
            mma_bf16(o[2 * dt + 1], pa[kc], b[2], b[3]);
        }
    }

    // ---- store ----
#pragma unroll
    for (int dj = 0; dj < 4; ++dj) {
        const int d = dj * 8 + t2;
        __nv_bfloat16* op0 = out + ((size_t)wnd * 64 + i0) * 192 + h * 32 + d;
        *(uint32_t*)op0             = pack_bf16(o[dj][0], o[dj][1]);
        *(uint32_t*)(op0 + 8 * 192) = pack_bf16(o[dj][2], o[dj][3]);
    }
}

// ---------------- launch --------------------------------------------------------
extern "C" void kernel_launch(void* const* d_in, const int* in_sizes, int n_in,
                              void* d_out, int out_size)
{
    const float* x    = (const float*)d_in[0];
    const float* g1   = (const float*)d_in[1];
    const float* b1   = (const float*)d_in[2];
    const float* wqkv = (const float*)d_in[3];
    const float* bqkv = (const float*)d_in[4];
    const float* wo   = (const float*)d_in[5];
    const float* bo   = (const float*)d_in[6];
    const float* bt   = (const float*)d_in[7];
    const float* g2   = (const float*)d_in[8];
    const float* b2   = (const float*)d_in[9];
    const float* w1   = (const float*)d_in[10];
    const float* bm1  = (const float*)d_in[11];
    const float* w2   = (const float*)d_in[12];
    const float* bm2  = (const float*)d_in[13];
    float* out = (float*)d_out;

    __nv_bfloat16 *p_xw, *p_qkv, *p_attn, *p_xn2, *p_h1;
    __nv_bfloat16 *p_wqkvt, *p_wot, *p_w1t, *p_w2t;
    float *p_xo;
    cudaGetSymbolAddress((void**)&p_xw,    g_xw);
    cudaGetSymbolAddress((void**)&p_qkv,   g_qkv);
    cudaGetSymbolAddress((void**)&p_attn,  g_attn);
    cudaGetSymbolAddress((void**)&p_xo,    g_xo);
    cudaGetSymbolAddress((void**)&p_xn2,   g_xn2);
    cudaGetSymbolAddress((void**)&p_h1,    g_h1);
    cudaGetSymbolAddress((void**)&p_wqkvt, g_wqkvt);
    cudaGetSymbolAddress((void**)&p_wot,   g_wot);
    cudaGetSymbolAddress((void**)&p_w1t,   g_w1t);
    cudaGetSymbolAddress((void**)&p_w2t,   g_w2t);

    cudaFuncSetAttribute(mma_gemm<0>, cudaFuncAttributeMaxDynamicSharedMemorySize, GSM_TOT);
    cudaFuncSetAttribute(mma_gemm<1>, cudaFuncAttributeMaxDynamicSharedMemorySize, GSM_TOT);
    cudaFuncSetAttribute(mma_gemm<2>, cudaFuncAttributeMaxDynamicSharedMemorySize, GSM_TOT);
    cudaFuncSetAttribute(mma_gemm<3>, cudaFuncAttributeMaxDynamicSharedMemorySize, GSM_TOT);

    wconv4<<<432, dim3(32, 8)>>>(wqkv, p_wqkvt, wo, p_wot, w1, p_w1t, w2, p_w2t);
    ln_kernel<<<NTOK / 8, 256>>>(x, g1, b1, p_xw);
    mma_gemm<0><<<dim3(3, NTOK / 64), 256, GSM_TOT>>>(p_xw, p_wqkvt, bqkv, p_qkv,
                                                      192, 576, nullptr, nullptr, nullptr, nullptr);
    attn_kernel<<<3072, 256>>>(p_qkv, bt, p_attn);
    mma_gemm<2><<<dim3(1, NTOK / 64), 256, GSM_TOT>>>(p_attn, p_wot, bo, p_xo,
                                                      192, 192, x, g2, b2, p_xn2);
    mma_gemm<1><<<dim3(4, NTOK / 64), 256, GSM_TOT>>>(p_xn2, p_w1t, bm1, p_h1,
                                                      192, 768, nullptr, nullptr, nullptr, nullptr);
    mma_gemm<3><<<dim3(1, NTOK / 64), 256, GSM_TOT>>>(p_h1, p_w2t, bm2, out,
                                                      768, 192, p_xo, nullptr, nullptr, nullptr);
}